// round 15
// baseline (speedup 1.0000x reference)
#include <cuda_runtime.h>
#include <cuda_fp16.h>
#include <cstdint>

#define SEQ   2048          // B*A
#define NT    121           // tokens
#define HDIM  128           // hidden
#define FIND  12            // feature in
#define NHEAD 4
#define HDH   32            // head dim
#define OUTD  256
#define MTOK  (SEQ*NT)      // 247808
#define KBIG  (NT*HDIM)     // 15488
#define SPLITK 11
#define NSTG  3
#define NSTQ  4
#define STGF  (128 * 20)
#define EPSV  1e-5f

// ---------------- scratch (device globals; no allocation allowed) ----------
__device__ float  g_x  [(size_t)MTOK * HDIM];
__device__ __half g_qkv[(size_t)MTOK * 384];
__device__ float  g_att[(size_t)MTOK * HDIM];
__device__ float  g_py [(size_t)SPLITK * SEQ * OUTD];

__device__ __forceinline__ void cpasync16(uint32_t dst, const float* src) {
    asm volatile("cp.async.cg.shared.global [%0], [%1], 16;" :: "r"(dst), "l"(src));
}
__device__ __forceinline__ uint32_t smem_u32(const void* p) {
    uint32_t a;
    asm("{ .reg .u64 t; cvta.to.shared.u64 t, %1; cvt.u32.u64 %0, t; }" : "=r"(a) : "l"(p));
    return a;
}

__device__ __forceinline__ void mma_tf32(float c[4], uint32_t a0, uint32_t a1,
                                         uint32_t a2, uint32_t a3,
                                         uint32_t b0, uint32_t b1) {
    asm volatile(
        "mma.sync.aligned.m16n8k8.row.col.f32.tf32.tf32.f32 "
        "{%0,%1,%2,%3},{%4,%5,%6,%7},{%8,%9},{%0,%1,%2,%3};\n"
        : "+f"(c[0]), "+f"(c[1]), "+f"(c[2]), "+f"(c[3])
        : "r"(a0), "r"(a1), "r"(a2), "r"(a3), "r"(b0), "r"(b1));
}

// ---------------- embed: 16 tokens per CTA, 128 threads --------------------
__global__ void embed_kernel(const float* __restrict__ forest,
                             const int*   __restrict__ perm,
                             const float* __restrict__ w_in,
                             const float* __restrict__ b_in,
                             float* __restrict__ out)
{
    int t0 = blockIdx.x * 16;
    int h = threadIdx.x;               // 128
    float w[FIND];
#pragma unroll
    for (int k = 0; k < FIND; k++) w[k] = w_in[h * FIND + k];
    float bh = b_in[h];
#pragma unroll 1
    for (int j = 0; j < 16; j++) {
        int tok = t0 + j;
        int s = tok / NT, i = tok - s * NT;
        int node = __ldg(&perm[i]);
        const float* f = forest + ((size_t)s * NT + node) * FIND;
        float acc = bh;
#pragma unroll
        for (int k = 0; k < FIND; k++) acc += __ldg(&f[k]) * w[k];
        if (h < 12) {
            int mask = 0, cur = node;
            while (cur > 0) {
                int d = (cur >= 40) ? 4 : (cur >= 13) ? 3 : (cur >= 4) ? 2 : 1;
                int br = (cur - 1) % 3;
                mask |= 1 << ((d - 1) * 3 + br);
                cur = (cur - 1) / 3;
            }
            acc += (float)((mask >> h) & 1);
        }
        out[(size_t)tok * HDIM + h] = acc;
    }
}

// ============ TF32 GEMM (split-K partial store only) =======================
struct MmSmem  { float As[NSTG][128][20]; float Bs[NSTG][128][20]; };

__global__ __launch_bounds__(256, 2)
void gemm_splitk_kernel(const float* __restrict__ X, const float* __restrict__ W,
                        float* __restrict__ C, int M, int Nc, int K, int kchunk)
{
    __shared__ MmSmem sm;
    int tid = threadIdx.x;
    int lane = tid & 31, warp = tid >> 5;
    int tq = lane >> 2, tr = lane & 3;
    int warpM = warp & 1, warpN = warp >> 1;
    int row0 = blockIdx.y * 128, col0 = blockIdx.x * 128;
    int kstart = blockIdx.z * kchunk;
    C += (size_t)blockIdx.z * M * Nc;

    int glr = tid >> 1;
    int glc = (tid & 1) * 8;
    const float* Xp = X + (size_t)(row0 + glr) * K + kstart + glc;
    const float* Wp = W + (size_t)(col0 + glr) * K + kstart + glc;
    uint32_t sa = smem_u32(&sm.As[0][glr][glc]);
    uint32_t sb = smem_u32(&sm.Bs[0][glr][glc]);
    const uint32_t STGB = STGF * 4;

    int nk16 = kchunk >> 4;

#pragma unroll
    for (int s = 0; s < NSTG - 1; s++) {
        if (s < nk16) {
            uint32_t so = (uint32_t)s * STGB;
            const float* xp = Xp + s * 16;
            const float* wp = Wp + s * 16;
            cpasync16(sa + so, xp);       cpasync16(sa + so + 16, xp + 4);
            cpasync16(sb + so, wp);       cpasync16(sb + so + 16, wp + 4);
        }
        asm volatile("cp.async.commit_group;");
    }
    asm volatile("cp.async.wait_group %0;" :: "n"(NSTG - 2));
    __syncthreads();

    float acc[4][4][4] = {};
    uint32_t af[2][4][4], bf[2][4][2];
    int arow = warpM * 64 + tq;
    int brow = warpN * 32 + tq;

#pragma unroll
    for (int mi = 0; mi < 4; mi++) {
        af[0][mi][0] = __float_as_uint(sm.As[0][arow + mi * 16    ][tr    ]);
        af[0][mi][1] = __float_as_uint(sm.As[0][arow + mi * 16 + 8][tr    ]);
        af[0][mi][2] = __float_as_uint(sm.As[0][arow + mi * 16    ][tr + 4]);
        af[0][mi][3] = __float_as_uint(sm.As[0][arow + mi * 16 + 8][tr + 4]);
    }
#pragma unroll
    for (int ni = 0; ni < 4; ni++) {
        bf[0][ni][0] = __float_as_uint(sm.Bs[0][brow + ni * 8][tr    ]);
        bf[0][ni][1] = __float_as_uint(sm.Bs[0][brow + ni * 8][tr + 4]);
    }

    int buf = 0, wslot = NSTG - 1;
    for (int kt = 0; kt < nk16; kt++) {
#pragma unroll
        for (int mi = 0; mi < 4; mi++) {
            af[1][mi][0] = __float_as_uint(sm.As[buf][arow + mi * 16    ][8 + tr    ]);
            af[1][mi][1] = __float_as_uint(sm.As[buf][arow + mi * 16 + 8][8 + tr    ]);
            af[1][mi][2] = __float_as_uint(sm.As[buf][arow + mi * 16    ][8 + tr + 4]);
            af[1][mi][3] = __float_as_uint(sm.As[buf][arow + mi * 16 + 8][8 + tr + 4]);
        }
#pragma unroll
        for (int ni = 0; ni < 4; ni++) {
            bf[1][ni][0] = __float_as_uint(sm.Bs[buf][brow + ni * 8][8 + tr    ]);
            bf[1][ni][1] = __float_as_uint(sm.Bs[buf][brow + ni * 8][8 + tr + 4]);
        }
#pragma unroll
        for (int mi = 0; mi < 4; mi++)
#pragma unroll
            for (int ni = 0; ni < 4; ni++)
                mma_tf32(acc[mi][ni], af[0][mi][0], af[0][mi][1],
                         af[0][mi][2], af[0][mi][3],
                         bf[0][ni][0], bf[0][ni][1]);
        int snext = kt + NSTG - 1;
        if (snext < nk16) {
            uint32_t so = (uint32_t)wslot * STGB;
            const float* xp = Xp + snext * 16;
            const float* wp = Wp + snext * 16;
            cpasync16(sa + so, xp);       cpasync16(sa + so + 16, xp + 4);
            cpasync16(sb + so, wp);       cpasync16(sb + so + 16, wp + 4);
        }
        asm volatile("cp.async.commit_group;");
        asm volatile("cp.async.wait_group %0;" :: "n"(NSTG - 2));
        __syncthreads();
        if (++wslot == NSTG) wslot = 0;
        int nb = buf + 1; if (nb == NSTG) nb = 0;
        if (kt + 1 < nk16) {
#pragma unroll
            for (int mi = 0; mi < 4; mi++) {
                af[0][mi][0] = __float_as_uint(sm.As[nb][arow + mi * 16    ][tr    ]);
                af[0][mi][1] = __float_as_uint(sm.As[nb][arow + mi * 16 + 8][tr    ]);
                af[0][mi][2] = __float_as_uint(sm.As[nb][arow + mi * 16    ][tr + 4]);
                af[0][mi][3] = __float_as_uint(sm.As[nb][arow + mi * 16 + 8][tr + 4]);
            }
#pragma unroll
            for (int ni = 0; ni < 4; ni++) {
                bf[0][ni][0] = __float_as_uint(sm.Bs[nb][brow + ni * 8][tr    ]);
                bf[0][ni][1] = __float_as_uint(sm.Bs[nb][brow + ni * 8][tr + 4]);
            }
        }
#pragma unroll
        for (int mi = 0; mi < 4; mi++)
#pragma unroll
            for (int ni = 0; ni < 4; ni++)
                mma_tf32(acc[mi][ni], af[1][mi][0], af[1][mi][1],
                         af[1][mi][2], af[1][mi][3],
                         bf[1][ni][0], bf[1][ni][1]);
        buf = nb;
    }

#pragma unroll
    for (int mi = 0; mi < 4; mi++)
#pragma unroll
        for (int h = 0; h < 2; h++) {
            int r = row0 + warpM * 64 + mi * 16 + tq + 8 * h;
#pragma unroll
            for (int ni = 0; ni < 4; ni++) {
                int c = col0 + warpN * 32 + ni * 8 + 2 * tr;
                *(float2*)&C[(size_t)r * Nc + c] =
                    make_float2(acc[mi][ni][2 * h], acc[mi][ni][2 * h + 1]);
            }
        }
}

// ========= QKV GEMM, smem-resident A, 4-stage B ring, half output ==========
#define QKV_DYN_BYTES (128 * 132 * 4 + NSTQ * STGF * 4)   // 67584 + 40960

__global__ __launch_bounds__(256, 2)
void qkv_kernel(const float* __restrict__ X, const float* __restrict__ W,
                const float* __restrict__ bias, __half* __restrict__ C)
{
    extern __shared__ float dsm[];
    float* Afull = dsm;                     // [128][132]
    float* BsR   = dsm + 128 * 132;         // [NSTQ][128][20]
#define QA(r, c)    Afull[(r) * 132 + (c)]
#define QB(s, r, c) BsR[(s) * STGF + (r) * 20 + (c)]

    int tid = threadIdx.x;
    int lane = tid & 31, warp = tid >> 5;
    int tq = lane >> 2, tr = lane & 3;
    int warpM = warp & 1, warpN = warp >> 1;
    int row0 = blockIdx.x * 128;

    uint32_t abase = smem_u32(&QA(0, 0));
    const float* Xb = X + (size_t)row0 * 128;
#pragma unroll
    for (int t = 0; t < 16; t++) {
        int m = tid + t * 256;
        int r = m >> 5, c4 = (m & 31) * 4;
        cpasync16(abase + (uint32_t)(r * 132 + c4) * 4, Xb + r * 128 + c4);
    }
    asm volatile("cp.async.commit_group;");

    int glr = tid >> 1, glc = (tid & 1) * 8;
    uint32_t sb = smem_u32(&QB(0, glr, glc));
    const uint32_t STGB = STGF * 4;

#pragma unroll
    for (int s = 0; s < 3; s++) {
        const float* wp = W + (size_t)glr * 128 + s * 16 + glc;
        cpasync16(sb + (uint32_t)s * STGB, wp);
        cpasync16(sb + (uint32_t)s * STGB + 16, wp + 4);
        asm volatile("cp.async.commit_group;");
    }
    asm volatile("cp.async.wait_group 2;");   // A + stage 0 complete
    __syncthreads();

    float acc[4][4][4] = {};
    uint32_t af[2][4][4], bf[2][4][2];
    int arow = warpM * 64 + tq;
    int brow = warpN * 32 + tq;

#pragma unroll
    for (int mi = 0; mi < 4; mi++) {
        af[0][mi][0] = __float_as_uint(QA(arow + mi * 16    , tr    ));
        af[0][mi][1] = __float_as_uint(QA(arow + mi * 16 + 8, tr    ));
        af[0][mi][2] = __float_as_uint(QA(arow + mi * 16    , tr + 4));
        af[0][mi][3] = __float_as_uint(QA(arow + mi * 16 + 8, tr + 4));
    }
#pragma unroll
    for (int ni = 0; ni < 4; ni++) {
        bf[0][ni][0] = __float_as_uint(QB(0, brow + ni * 8, tr    ));
        bf[0][ni][1] = __float_as_uint(QB(0, brow + ni * 8, tr + 4));
    }

    for (int g = 0; g < 24; g++) {
        int kt = g & 7;
        int buf = g & (NSTQ - 1);
        int kb = kt * 16;
#pragma unroll
        for (int mi = 0; mi < 4; mi++) {
            af[1][mi][0] = __float_as_uint(QA(arow + mi * 16    , kb + 8 + tr    ));
            af[1][mi][1] = __float_as_uint(QA(arow + mi * 16 + 8, kb + 8 + tr    ));
            af[1][mi][2] = __float_as_uint(QA(arow + mi * 16    , kb + 8 + tr + 4));
            af[1][mi][3] = __float_as_uint(QA(arow + mi * 16 + 8, kb + 8 + tr + 4));
        }
#pragma unroll
        for (int ni = 0; ni < 4; ni++) {
            bf[1][ni][0] = __float_as_uint(QB(buf, brow + ni * 8, 8 + tr    ));
            bf[1][ni][1] = __float_as_uint(QB(buf, brow + ni * 8, 8 + tr + 4));
        }
#pragma unroll
        for (int mi = 0; mi < 4; mi++)
#pragma unroll
            for (int ni = 0; ni < 4; ni++)
                mma_tf32(acc[mi][ni], af[0][mi][0], af[0][mi][1],
                         af[0][mi][2], af[0][mi][3],
                         bf[0][ni][0], bf[0][ni][1]);
        int gn = g + 3;
        if (gn < 24) {
            int ctn = gn >> 3, ktn = gn & 7;
            const float* wp = W + (size_t)(ctn * 128 + glr) * 128 + ktn * 16 + glc;
            uint32_t so = (uint32_t)(gn & (NSTQ - 1)) * STGB;
            cpasync16(sb + so, wp);   cpasync16(sb + so + 16, wp + 4);
        }
        asm volatile("cp.async.commit_group;");
        asm volatile("cp.async.wait_group 2;");
        __syncthreads();
        if (g + 1 < 24) {
            int k2 = ((g + 1) & 7) * 16;
            int b2 = (g + 1) & (NSTQ - 1);
#pragma unroll
            for (int mi = 0; mi < 4; mi++) {
                af[0][mi][0] = __float_as_uint(QA(arow + mi * 16    , k2 + tr    ));
                af[0][mi][1] = __float_as_uint(QA(arow + mi * 16 + 8, k2 + tr    ));
                af[0][mi][2] = __float_as_uint(QA(arow + mi * 16    , k2 + tr + 4));
                af[0][mi][3] = __float_as_uint(QA(arow + mi * 16 + 8, k2 + tr + 4));
            }
#pragma unroll
            for (int ni = 0; ni < 4; ni++) {
                bf[0][ni][0] = __float_as_uint(QB(b2, brow + ni * 8, tr    ));
                bf[0][ni][1] = __float_as_uint(QB(b2, brow + ni * 8, tr + 4));
            }
        }
#pragma unroll
        for (int mi = 0; mi < 4; mi++)
#pragma unroll
            for (int ni = 0; ni < 4; ni++)
                mma_tf32(acc[mi][ni], af[1][mi][0], af[1][mi][1],
                         af[1][mi][2], af[1][mi][3],
                         bf[1][ni][0], bf[1][ni][1]);
        if (kt == 7) {
            int cb = (g >> 3) * 128;
#pragma unroll
            for (int mi = 0; mi < 4; mi++)
#pragma unroll
                for (int h = 0; h < 2; h++) {
                    int r = row0 + warpM * 64 + mi * 16 + tq + 8 * h;
#pragma unroll
                    for (int ni = 0; ni < 4; ni++) {
                        int c = warpN * 32 + ni * 8 + 2 * tr;
                        float v0 = acc[mi][ni][2 * h]     + bias[cb + c];
                        float v1 = acc[mi][ni][2 * h + 1] + bias[cb + c + 1];
                        *(__half2*)&C[(size_t)r * 384 + cb + c] =
                            __floats2half2_rn(v0, v1);
                        acc[mi][ni][2 * h] = 0.f;
                        acc[mi][ni][2 * h + 1] = 0.f;
                    }
                }
        }
    }
#undef QA
#undef QB
}

// ===== proj: resident-A GEMM + bias + residual + LayerNorm (in-place X) ====
#define PROJ_DYN_BYTES (128 * 132 * 4 + NSTQ * STGF * 4)

__global__ __launch_bounds__(256, 2)
void proj_kernel(const float* __restrict__ AB, const float* __restrict__ W,
                 const float* __restrict__ bias,
                 const float* __restrict__ lng, const float* __restrict__ lnb,
                 float* __restrict__ X)
{
    extern __shared__ float dsm[];
    float* Afull = dsm;                     // [128][132]
    float* BsR   = dsm + 128 * 132;         // [NSTQ][128][20]
#define PA(r, c)    Afull[(r) * 132 + (c)]
#define PB(s, r, c) BsR[(s) * STGF + (r) * 20 + (c)]

    int tid = threadIdx.x;
    int lane = tid & 31, warp = tid >> 5;
    int tq = lane >> 2, tr = lane & 3;
    int warpM = warp & 1, warpN = warp >> 1;
    int row0 = blockIdx.x * 128;

    uint32_t abase = smem_u32(&PA(0, 0));
    const float* Ab = AB + (size_t)row0 * 128;
#pragma unroll
    for (int t = 0; t < 16; t++) {
        int m = tid + t * 256;
        int r = m >> 5, c4 = (m & 31) * 4;
        cpasync16(abase + (uint32_t)(r * 132 + c4) * 4, Ab + r * 128 + c4);
    }
    asm volatile("cp.async.commit_group;");

    int glr = tid >> 1, glc = (tid & 1) * 8;
    uint32_t sb = smem_u32(&PB(0, glr, glc));
    const uint32_t STGB = STGF * 4;

#pragma unroll
    for (int s = 0; s < 3; s++) {
        const float* wp = W + (size_t)glr * 128 + s * 16 + glc;
        cpasync16(sb + (uint32_t)s * STGB, wp);
        cpasync16(sb + (uint32_t)s * STGB + 16, wp + 4);
        asm volatile("cp.async.commit_group;");
    }
    asm volatile("cp.async.wait_group 2;");   // A + stage 0 complete
    __syncthreads();

    float acc[4][4][4] = {};
    uint32_t af[2][4][4], bf[2][4][2];
    int arow = warpM * 64 + tq;
    int brow = warpN * 32 + tq;

#pragma unroll
    for (int mi = 0; mi < 4; mi++) {
        af[0][mi][0] = __float_as_uint(PA(arow + mi * 16    , tr    ));
        af[0][mi][1] = __float_as_uint(PA(arow + mi * 16 + 8, tr    ));
        af[0][mi][2] = __float_as_uint(PA(arow + mi * 16    , tr + 4));
        af[0][mi][3] = __float_as_uint(PA(arow + mi * 16 + 8, tr + 4));
    }
#pragma unroll
    for (int ni = 0; ni < 4; ni++) {
        bf[0][ni][0] = __float_as_uint(PB(0, brow + ni * 8, tr    ));
        bf[0][ni][1] = __float_as_uint(PB(0, brow + ni * 8, tr + 4));
    }

    for (int g = 0; g < 8; g++) {
        int buf = g & (NSTQ - 1);
        int kb = g * 16;
#pragma unroll
        for (int mi = 0; mi < 4; mi++) {
            af[1][mi][0] = __float_as_uint(PA(arow + mi * 16    , kb + 8 + tr    ));
            af[1][mi][1] = __float_as_uint(PA(arow + mi * 16 + 8, kb + 8 + tr    ));
            af[1][mi][2] = __float_as_uint(PA(arow + mi * 16    , kb + 8 + tr + 4));
            af[1][mi][3] = __float_as_uint(PA(arow + mi * 16 + 8, kb + 8 + tr + 4));
        }
#pragma unroll
        for (int ni = 0; ni < 4; ni++) {
            bf[1][ni][0] = __float_as_uint(PB(buf, brow + ni * 8, 8 + tr    ));
            bf[1][ni][1] = __float_as_uint(PB(buf, brow + ni * 8, 8 + tr + 4));
        }
#pragma unroll
        for (int mi = 0; mi < 4; mi++)
#pragma unroll
            for (int ni = 0; ni < 4; ni++)
                mma_tf32(acc[mi][ni], af[0][mi][0], af[0][mi][1],
                         af[0][mi][2], af[0][mi][3],
                         bf[0][ni][0], bf[0][ni][1]);
        int gn = g + 3;
        if (gn < 8) {
            const float* wp = W + (size_t)glr * 128 + gn * 16 + glc;
            uint32_t so = (uint32_t)(gn & (NSTQ - 1)) * STGB;
            cpasync16(sb + so, wp);   cpasync16(sb + so + 16, wp + 4);
        }
        asm volatile("cp.async.commit_group;");
        asm volatile("cp.async.wait_group 2;");
        __syncthreads();
        if (g + 1 < 8) {
            int k2 = (g + 1) * 16;
            int b2 = (g + 1) & (NSTQ - 1);
#pragma unroll
            for (int mi = 0; mi < 4; mi++) {
                af[0][mi][0] = __float_as_uint(PA(arow + mi * 16    , k2 + tr    ));
                af[0][mi][1] = __float_as_uint(PA(arow + mi * 16 + 8, k2 + tr    ));
                af[0][mi][2] = __float_as_uint(PA(arow + mi * 16    , k2 + tr + 4));
                af[0][mi][3] = __float_as_uint(PA(arow + mi * 16 + 8, k2 + tr + 4));
            }
#pragma unroll
            for (int ni = 0; ni < 4; ni++) {
                bf[0][ni][0] = __float_as_uint(PB(b2, brow + ni * 8, tr    ));
                bf[0][ni][1] = __float_as_uint(PB(b2, brow + ni * 8, tr + 4));
            }
        }
#pragma unroll
        for (int mi = 0; mi < 4; mi++)
#pragma unroll
            for (int ni = 0; ni < 4; ni++)
                mma_tf32(acc[mi][ni], af[1][mi][0], af[1][mi][1],
                         af[1][mi][2], af[1][mi][3],
                         bf[1][ni][0], bf[1][ni][1]);
    }

    // epilogue: + bias + residual X, LayerNorm, write X (in place)
    __syncthreads();                  // all warps done with B ring
    float* red  = BsR;                // [128][17] in dead ring memory
    float* stat = BsR + 128 * 17;
#pragma unroll
    for (int mi = 0; mi < 4; mi++)
#pragma unroll
        for (int h = 0; h < 2; h++) {
            int r = row0 + warpM * 64 + mi * 16 + tq + 8 * h;
#pragma unroll
            for (int ni = 0; ni < 4; ni++) {
                int c = warpN * 32 + ni * 8 + 2 * tr;
                float2 rv = *(const float2*)&X[(size_t)r * 128 + c];
                acc[mi][ni][2 * h]     += bias[c]     + rv.x;
                acc[mi][ni][2 * h + 1] += bias[c + 1] + rv.y;
            }
        }
    int cid = warpN * 4 + tr;
#pragma unroll
    for (int mi = 0; mi < 4; mi++)
#pragma unroll
        for (int h = 0; h < 2; h++) {
            int rl = warpM * 64 + mi * 16 + tq + 8 * h;
            float s = 0.f;
#pragma unroll
            for (int ni = 0; ni < 4; ni++) s += acc[mi][ni][2 * h] + acc[mi][ni][2 * h + 1];
            red[rl * 17 + cid] = s;
        }
    __syncthreads();
    if (tid < 128) {
        float s = 0.f;
#pragma unroll
        for (int t = 0; t < 16; t++) s += red[tid * 17 + t];
        stat[tid] = s * (1.f / 128.f);
    }
    __syncthreads();
    float mean[4][2];
#pragma unroll
    for (int mi = 0; mi < 4; mi++)
#pragma unroll
        for (int h = 0; h < 2; h++)
            mean[mi][h] = stat[warpM * 64 + mi * 16 + tq + 8 * h];
    __syncthreads();
#pragma unroll
    for (int mi = 0; mi < 4; mi++)
#pragma unroll
        for (int h = 0; h < 2; h++) {
            int rl = warpM * 64 + mi * 16 + tq + 8 * h;
            float s = 0.f;
#pragma unroll
            for (int ni = 0; ni < 4; ni++) {
                float d0 = acc[mi][ni][2 * h]     - mean[mi][h];
                float d1 = acc[mi][ni][2 * h + 1] - mean[mi][h];
                s += d0 * d0 + d1 * d1;
            }
            red[rl * 17 + cid] = s;
        }
    __syncthreads();
    if (tid < 128) {
        float s = 0.f;
#pragma unroll
        for (int t = 0; t < 16; t++) s += red[tid * 17 + t];
        stat[tid] = rsqrtf(s * (1.f / 128.f) + EPSV);
    }
    __syncthreads();
#pragma unroll
    for (int mi = 0; mi < 4; mi++)
#pragma unroll
        for (int h = 0; h < 2; h++) {
            int rl = warpM * 64 + mi * 16 + tq + 8 * h;
            int r = row0 + rl;
            float rs = stat[rl];
#pragma unroll
            for (int ni = 0; ni < 4; ni++) {
                int c = warpN * 32 + ni * 8 + 2 * tr;
                float v0 = (acc[mi][ni][2 * h]     - mean[mi][h]) * rs * lng[c]     + lnb[c];
                float v1 = (acc[mi][ni][2 * h + 1] - mean[mi][h]) * rs * lng[c + 1] + lnb[c + 1];
                *(float2*)&X[(size_t)r * 128 + c] = make_float2(v0, v1);
            }
        }
#undef PA
#undef PB
}

// ======== tensor-core attention (half QKV in), one CTA per (seq, head) =====
#define ATTN_SMEM_FLOATS (128 * 132 + 32 * 132)
#define ATTN_SMEM_BYTES  (ATTN_SMEM_FLOATS * 4)

__global__ __launch_bounds__(256)
void attn_mma_kernel(const __half* __restrict__ qkv, float* __restrict__ out)
{
    extern __shared__ float smf[];
    float (*qs)[36]  = (float(*)[36])smf;
    float (*ks)[36]  = (float(*)[36])(smf + 128 * 36);
    float (*sp)[132] = (float(*)[132])smf;
    float (*vt)[132] = (float(*)[132])(smf + 128 * 132);

    int s  = blockIdx.x >> 2;
    int hh = blockIdx.x & 3;
    int tid = threadIdx.x;
    int lane = tid & 31, warp = tid >> 5;
    int tq = lane >> 2, tr = lane & 3;
    int warpM = warp & 1, warpN = warp >> 1;

    for (int idx = tid; idx < 7 * 36; idx += 256) {
        int r = 121 + idx / 36, c = idx % 36;
        qs[r][c] = 0.f;
        ks[r][c] = 0.f;
    }
    for (int idx = tid; idx < 32 * 7; idx += 256) {
        int d = idx / 7, c = 121 + idx % 7;
        vt[d][c] = 0.f;
    }

    const __half* base = qkv + (size_t)s * NT * 384 + hh * HDH;
    for (int idx = tid; idx < NT * 8; idx += 256) {
        int n = idx >> 3, d4 = (idx & 7) * 4;
        const __half* bp = base + (size_t)n * 384 + d4;
        float2 q01 = __half22float2(*(const __half2*)(bp));
        float2 q23 = __half22float2(*(const __half2*)(bp + 2));
        float2 k01 = __half22float2(*(const __half2*)(bp + 128));
        float2 k23 = __half22float2(*(const __half2*)(bp + 130));
        float2 v01 = __half22float2(*(const __half2*)(bp + 256));
        float2 v23 = __half22float2(*(const __half2*)(bp + 258));
        qs[n][d4 + 0] = q01.x; qs[n][d4 + 1] = q01.y;
        qs[n][d4 + 2] = q23.x; qs[n][d4 + 3] = q23.y;
        ks[n][d4 + 0] = k01.x; ks[n][d4 + 1] = k01.y;
        ks[n][d4 + 2] = k23.x; ks[n][d4 + 3] = k23.y;
        vt[d4 + 0][n] = v01.x;
        vt[d4 + 1][n] = v01.y;
        vt[d4 + 2][n] = v23.x;
        vt[d4 + 3][n] = v23.y;
    }
    __syncthreads();

    float acc[4][4][4] = {};
#pragma unroll
    for (int k8 = 0; k8 < 32; k8 += 8) {
        uint32_t af[4][4], bf[4][2];
#pragma unroll
        for (int mi = 0; mi < 4; mi++) {
            int ar = warpM * 64 + mi * 16 + tq;
            af[mi][0] = __float_as_uint(qs[ar    ][k8 + tr    ]);
            af[mi][1] = __float_as_uint(qs[ar + 8][k8 + tr    ]);
            af[mi][2] = __float_as_uint(qs[ar    ][k8 + tr + 4]);
            af[mi][3] = __float_as_uint(qs[ar + 8][k8 + tr + 4]);
        }
#pragma unroll
        for (int ni = 0; ni < 4; ni++) {
            int br = warpN * 32 + ni * 8 + tq;
            bf[ni][0] = __float_as_uint(ks[br][k8 + tr    ]);
            bf[ni][1] = __float_as_uint(ks[br][k8 + tr + 4]);
        }
#pragma unroll
        for (int mi = 0; mi < 4; mi++)
#pragma unroll
            for (int ni = 0; ni < 4; ni++)
                mma_tf32(acc[mi][ni], af[mi][0], af[mi][1], af[mi][2], af[mi][3],
                         bf[ni][0], bf[ni][1]);
    }
    __syncthreads();

#pragma unroll
    for (int mi = 0; mi < 4; mi++)
#pragma unroll
        for (int h = 0; h < 2; h++) {
            int r = warpM * 64 + mi * 16 + tq + 8 * h;
#pragma unroll
            for (int ni = 0; ni < 4; ni++) {
                int c = warpN * 32 + ni * 8 + 2 * tr;
                *(float2*)&sp[r][c] = make_float2(acc[mi][ni][2 * h], acc[mi][ni][2 * h + 1]);
            }
        }
    __syncthreads();

    const float scale = 0.17677669529663687f;
    if (tid < 128) {
        float mx = -1e30f;
        for (int c = 0; c < NT; c++) mx = fmaxf(mx, sp[tid][c]);
        float sum = 0.f;
        for (int c = 0; c < NT; c++) {
            float e = __expf((sp[tid][c] - mx) * scale);
            sp[tid][c] = e;
            sum += e;
        }
        float inv = 1.f / sum;
        for (int c = 0; c < NT; c++) sp[tid][c] *= inv;
#pragma unroll
        for (int c = NT; c < 128; c++) sp[tid][c] = 0.f;
    }
    __syncthreads();

    float pacc[4][4] = {};
#pragma unroll
    for (int k8 = 0; k8 < 128; k8 += 8) {
        uint32_t af[4][4], bf[2];
#pragma unroll
        for (int mi = 0; mi < 4; mi++) {
            int ar = warpM * 64 + mi * 16 + tq;
            af[mi][0] = __float_as_uint(sp[ar    ][k8 + tr    ]);
            af[mi][1] = __float_as_uint(sp[ar + 8][k8 + tr    ]);
            af[mi][2] = __float_as_uint(sp[ar    ][k8 + tr + 4]);
            af[mi][3] = __float_as_uint(sp[ar + 8][k8 + tr + 4]);
        }
        int bn = warpN * 8 + tq;
        bf[0] = __float_as_uint(vt[bn][k8 + tr    ]);
        bf[1] = __float_as_uint(vt[bn][k8 + tr + 4]);
#pragma unroll
        for (int mi = 0; mi < 4; mi++)
            mma_tf32(pacc[mi], af[mi][0], af[mi][1], af[mi][2], af[mi][3],
                     bf[0], bf[1]);
    }

#pragma unroll
    for (int mi = 0; mi < 4; mi++)
#pragma unroll
        for (int h = 0; h < 2; h++) {
            int r = warpM * 64 + mi * 16 + tq + 8 * h;
            if (r < NT) {
                int c = warpN * 8 + 2 * tr;
                *(float2*)&out[((size_t)s * NT + r) * HDIM + hh * HDH + c] =
                    make_float2(pacc[mi][2 * h], pacc[mi][2 * h + 1]);
            }
        }
}

// ========== fused FFN: x = LN(x + relu(x@W1^T+b1)@W2^T + b2) ==============
#define FFN_DYN_BYTES (NSTG * STGF * 4 + 128 * 132 * 4)   // 30720 + 67584

__global__ __launch_bounds__(256, 2)
void ffn_kernel(const float* __restrict__ X,
                const float* __restrict__ W1, const float* __restrict__ b1,
                const float* __restrict__ W2, const float* __restrict__ b2,
                const float* __restrict__ lng, const float* __restrict__ lnb,
                float* __restrict__ C)
{
    extern __shared__ float dsm[];
    float* BsR = dsm;
    float* AR  = dsm + NSTG * STGF;
#define FB(s, r, c) BsR[(s) * STGF + (r) * 20 + (c)]
#define FA(s, r, c) AR[(s) * STGF + (r) * 20 + (c)]
#define HS(r, c)    AR[(r) * 132 + (c)]

    int tid = threadIdx.x;
    int lane = tid & 31, warp = tid >> 5;
    int tq = lane >> 2, tr = lane & 3;
    int warpM = warp & 1, warpN = warp >> 1;
    int row0 = blockIdx.x * 128;

    int glr = tid >> 1;
    int glc = (tid & 1) * 8;
    const float* Xp  = X  + (size_t)(row0 + glr) * 128 + glc;
    const float* W1p = W1 + (size_t)glr * 128 + glc;
    const float* W2p = W2 + (size_t)glr * 128 + glc;
    uint32_t sa = smem_u32(&FA(0, glr, glc));
    uint32_t sb = smem_u32(&FB(0, glr, glc));
    const uint32_t STGB = STGF * 4;

    int arow = warpM * 64 + tq;
    int brow = warpN * 32 + tq;
    float acc[4][4][4] = {};
    uint32_t af[2][4][4], bf[2][4][2];

#pragma unroll
    for (int s = 0; s < NSTG - 1; s++) {
        uint32_t so = (uint32_t)s * STGB;
        cpasync16(sa + so, Xp + s * 16);       cpasync16(sa + so + 16, Xp + s * 16 + 4);
        cpasync16(sb + so, W1p + s * 16);      cpasync16(sb + so + 16, W1p + s * 16 + 4);
        asm volatile("cp.async.commit_group;");
    }
    asm volatile("cp.async.wait_group %0;" :: "n"(NSTG - 2));
    __syncthreads();

#pragma unroll
    for (int mi = 0; mi < 4; mi++) {
        af[0][mi][0] = __float_as_uint(FA(0, arow + mi * 16    , tr    ));
        af[0][mi][1] = __float_as_uint(FA(0, arow + mi * 16 + 8, tr    ));
        af[0][mi][2] = __float_as_uint(FA(0, arow + mi * 16    , tr + 4));
        af[0][mi][3] = __float_as_uint(FA(0, arow + mi * 16 + 8, tr + 4));
    }
#pragma unroll
    for (int ni = 0; ni < 4; ni++) {
        bf[0][ni][0] = __float_as_uint(FB(0, brow + ni * 8, tr    ));
        bf[0][ni][1] = __float_as_uint(FB(0, brow + ni * 8, tr + 4));
    }

    int buf = 0, wslot = NSTG - 1;
    for (int kt = 0; kt < 8; kt++) {
#pragma unroll
        for (int mi = 0; mi < 4; mi++) {
            af[1][mi][0] = __float_as_uint(FA(buf, arow + mi * 16    , 8 + tr    ));
            af[1][mi][1] = __float_as_uint(FA(buf, arow + mi * 16 + 8, 8 + tr    ));
            af[1][mi][2] = __float_as_uint(FA(buf, arow + mi * 16    , 8 + tr + 4));
            af[1][mi][3] = __float_as_uint(FA(buf, arow + mi * 16 + 8, 8 + tr + 4));
        }
#pragma unroll
        for (int ni = 0; ni < 4; ni++) {
            bf[1][ni][0] = __float_as_uint(FB(buf, brow + ni * 8, 8 + tr    ));
            bf[1][ni][1] = __float_as_uint(FB(buf, brow + ni * 8, 8 + tr + 4));
        }
#pragma unroll
        for (int mi = 0; mi < 4; mi++)
#pragma unroll
            for (int ni = 0; ni < 4; ni++)
                mma_tf32(acc[mi][ni], af[0][mi][0], af[0][mi][1],
                         af[0][mi][2], af[0][mi][3],
                         bf[0][ni][0], bf[0][ni][1]);
        int snext = kt + NSTG - 1;
        if (snext < 8) {
            uint32_t so = (uint32_t)wslot * STGB;
            cpasync16(sa + so, Xp + snext * 16);   cpasync16(sa + so + 16, Xp + snext * 16 + 4);
            cpasync16(sb + so, W1p + snext * 16);  cpasync16(sb + so + 16, W1p + snext * 16 + 4);
        }
        asm volatile("cp.async.commit_group;");
        asm volatile("cp.async.wait_group %0;" :: "n"(NSTG - 2));
        __syncthreads();
        if (++wslot == NSTG) wslot = 0;
        int nb = buf + 1; if (nb == NSTG) nb = 0;
        if (kt + 1 < 8) {
#pragma unroll
            for (int mi = 0; mi < 4; mi++) {
                af[0][mi][0] = __float_as_uint(FA(nb, arow + mi * 16    , tr    ));
                af[0][mi][1] = __float_as_uint(FA(nb, arow + mi * 16 + 8, tr    ));
                af[0][mi][2] = __float_as_uint(FA(nb, arow + mi * 16    , tr + 4));
                af[0][mi][3] = __float_as_uint(FA(nb, arow + mi * 16 + 8, tr + 4));
            }
#pragma unroll
            for (int ni = 0; ni < 4; ni++) {
                bf[0][ni][0] = __float_as_uint(FB(nb, brow + ni * 8, tr    ));
                bf[0][ni][1] = __float_as_uint(FB(nb, brow + ni * 8, tr + 4));
            }
        }
#pragma unroll
        for (int mi = 0; mi < 4; mi++)
#pragma unroll
            for (int ni = 0; ni < 4; ni++)
                mma_tf32(acc[mi][ni], af[1][mi][0], af[1][mi][1],
                         af[1][mi][2], af[1][mi][3],
                         bf[1][ni][0], bf[1][ni][1]);
        buf = nb;
    }

#pragma unroll
    for (int s = 0; s < NSTG - 1; s++) {
        uint32_t so = (uint32_t)s * STGB;
        cpasync16(sb + so, W2p + s * 16);      cpasync16(sb + so + 16, W2p + s * 16 + 4);
        asm volatile("cp.async.commit_group;");
    }

#pragma unroll
    for (int mi = 0; mi < 4; mi++)
#pragma unroll
        for (int h2 = 0; h2 < 2; h2++) {
            int r = warpM * 64 + mi * 16 + tq + 8 * h2;
#pragma unroll
            for (int ni = 0; ni < 4; ni++) {
                int c = warpN * 32 + ni * 8 + 2 * tr;
                HS(r, c)     = fmaxf(acc[mi][ni][2 * h2]     + b1[c],     0.f);
                HS(r, c + 1) = fmaxf(acc[mi][ni][2 * h2 + 1] + b1[c + 1], 0.f);
            }
        }
    asm volatile("cp.async.wait_group %0;" :: "n"(NSTG - 2));
    __syncthreads();

#pragma unroll
    for (int mi = 0; mi < 4; mi++)
#pragma unroll
        for (int ni = 0; ni < 4; ni++)
#pragma unroll
            for (int q = 0; q < 4; q++) acc[mi][ni][q] = 0.f;

#pragma unroll
    for (int mi = 0; mi < 4; mi++) {
        af[0][mi][0] = __float_as_uint(HS(arow + mi * 16    , tr    ));
        af[0][mi][1] = __float_as_uint(HS(arow + mi * 16 + 8, tr    ));
        af[0][mi][2] = __float_as_uint(HS(arow + mi * 16    , tr + 4));
        af[0][mi][3] = __float_as_uint(HS(arow + mi * 16 + 8, tr + 4));
    }
#pragma unroll
    for (int ni = 0; ni < 4; ni++) {
        bf[0][ni][0] = __float_as_uint(FB(0, brow + ni * 8, tr    ));
        bf[0][ni][1] = __float_as_uint(FB(0, brow + ni * 8, tr + 4));
    }

    buf = 0; wslot = NSTG - 1;
    for (int kt = 0; kt < 8; kt++) {
        int kb = kt * 16;
#pragma unroll
        for (int mi = 0; mi < 4; mi++) {
            af[1][mi][0] = __float_as_uint(HS(arow + mi * 16    , kb + 8 + tr    ));
            af[1][mi][1] = __float_as_uint(HS(arow + mi * 16 + 8, kb + 8 + tr    ));
            af[1][mi][2] = __float_as_uint(HS(arow + mi * 16    , kb + 8 + tr + 4));
            af[1][mi][3] = __float_as_uint(HS(arow + mi * 16 + 8, kb + 8 + tr + 4));
        }
#pragma unroll
        for (int ni = 0; ni < 4; ni++) {
            bf[1][ni][0] = __float_as_uint(FB(buf, brow + ni * 8, 8 + tr    ));
            bf[1][ni][1] = __float_as_uint(FB(buf, brow + ni * 8, 8 + tr + 4));
        }
#pragma unroll
        for (int mi = 0; mi < 4; mi++)
#pragma unroll
            for (int ni = 0; ni < 4; ni++)
                mma_tf32(acc[mi][ni], af[0][mi][0], af[0][mi][1],
                         af[0][mi][2], af[0][mi][3],
                         bf[0][ni][0], bf[0][ni][1]);
        int snext = kt + NSTG - 1;
        if (snext < 8) {
            uint32_t so = (uint32_t)wslot * STGB;
            cpasync16(sb + so, W2p + snext * 16);  cpasync16(sb + so + 16, W2p + snext * 16 + 4);
        }
        asm volatile("cp.async.commit_group;");
        asm volatile("cp.async.wait_group %0;" :: "n"(NSTG - 2));
        __syncthreads();
        if (++wslot == NSTG) wslot = 0;
        int nb = buf + 1; if (nb == NSTG) nb = 0;
        if (kt + 1 < 8) {
            int kn = (kt + 1) * 16;
#pragma unroll
            for (int mi = 0; mi < 4; mi++) {
                af[0][mi][0] = __float_as_uint(HS(arow + mi * 16    , kn + tr    ));
                af[0][mi][1] = __float_as_uint(HS(arow + mi * 16 + 8, kn + tr    ));
                af[0][mi][2] = __float_as_uint(HS(arow + mi * 16    , kn + tr + 4));
                af[0][mi][3] = __float_as_uint(HS(arow + mi * 16 + 8, kn + tr + 4));
            }
#pragma unroll
            for (int ni = 0; ni < 4; ni++) {
                bf[0][ni][0] = __float_as_uint(FB(nb, brow + ni * 8, tr    ));
                bf[0][ni][1] = __float_as_uint(FB(nb, brow + ni * 8, tr + 4));
            }
        }
#pragma unroll
        for (int mi = 0; mi < 4; mi++)
#pragma unroll
            for (int ni = 0; ni < 4; ni++)
                mma_tf32(acc[mi][ni], af[1][mi][0], af[1][mi][1],
                         af[1][mi][2], af[1][mi][3],
                         bf[1][ni][0], bf[1][ni][1]);
        buf = nb;
    }

    float* red  = dsm;
    float* stat = dsm + 128 * 17;
#pragma unroll
    for (int mi = 0; mi < 4; mi++)
#pragma unroll
        for (int h2 = 0; h2 < 2; h2++) {
            int r = row0 + warpM * 64 + mi * 16 + tq + 8 * h2;
#pragma unroll
            for (int ni = 0; ni < 4; ni++) {
                int c = warpN * 32 + ni * 8 + 2 * tr;
                float2 rv = *(const float2*)&X[(size_t)r * 128 + c];
                acc[mi][ni][2 * h2]     += b2[c]     + rv.x;
                acc[mi][ni][2 * h2 + 1] += b2[c + 1] + rv.y;
            }
        }
    __syncthreads();
    int cid = warpN * 4 + tr;
#pragma unroll
    for (int mi = 0; mi < 4; mi++)
#pragma unroll
        for (int h2 = 0; h2 < 2; h2++) {
            int rl = warpM * 64 + mi * 16 + tq + 8 * h2;
            float s = 0.f;
#pragma unroll
            for (int ni = 0; ni < 4; ni++) s += acc[mi][ni][2 * h2] + acc[mi][ni][2 * h2 + 1];
            red[rl * 17 + cid] = s;
        }
    __syncthreads();
    if (tid < 128) {
        float s = 0.f;
#pragma unroll
        for (int t = 0; t < 16; t++) s += red[tid * 17 + t];
        stat[tid] = s * (1.f / 128.f);
    }
    __syncthreads();
    float mean[4][2];
#pragma unroll
    for (int mi = 0; mi < 4; mi++)
#pragma unroll
        for (int h2 = 0; h2 < 2; h2++)
            mean[mi][h2] = stat[warpM * 64 + mi * 16 + tq + 8 * h2];
    __syncthreads();
#pragma unroll
    for (int mi = 0; mi < 4; mi++)
#pragma unroll
        for (int h2 = 0; h2 < 2; h2++) {
            int rl = warpM * 64 + mi * 16 + tq + 8 * h2;
            float s = 0.f;
#pragma unroll
            for (int ni = 0; ni < 4; ni++) {
                float d0 = acc[mi][ni][2 * h2]     - mean[mi][h2];
                float d1 = acc[mi][ni][2 * h2 + 1] - mean[mi][h2];
                s += d0 * d0 + d1 * d1;
            }
            red[rl * 17 + cid] = s;
        }
    __syncthreads();
    if (tid < 128) {
        float s = 0.f;
#pragma unroll
        for (int t = 0; t < 16; t++) s += red[tid * 17 + t];
        stat[tid] = rsqrtf(s * (1.f / 128.f) + EPSV);
    }
    __syncthreads();
#pragma unroll
    for (int mi = 0; mi < 4; mi++)
#pragma unroll
        for (int h2 = 0; h2 < 2; h2++) {
            int rl = warpM * 64 + mi * 16 + tq + 8 * h2;
            int r = row0 + rl;
            float rs = stat[rl];
#pragma unroll
            for (int ni = 0; ni < 4; ni++) {
                int c = warpN * 32 + ni * 8 + 2 * tr;
                float v0 = (acc[mi][ni][2 * h2]     - mean[mi][h2]) * rs * lng[c]     + lnb[c];
                float v1 = (acc[mi][ni][2 * h2 + 1] - mean[mi][h2]) * rs * lng[c + 1] + lnb[c + 1];
                *(float2*)&C[(size_t)r * 128 + c] = make_float2(v0, v1);
            }
        }
#undef FB
#undef FA
#undef HS
}

// ------- final: reduce split-K partials + bias + LayerNorm over 256 -------
__global__ void out_ln_kernel(const float* __restrict__ part,
                              const float* __restrict__ b_out,
                              const float* __restrict__ g,
                              const float* __restrict__ b,
                              float* __restrict__ out)
{
    int row = blockIdx.x, t = threadIdx.x;
    size_t idx = (size_t)row * OUTD + t;
    float v = b_out[t];
#pragma unroll
    for (int z = 0; z < SPLITK; z++) v += part[(size_t)z * SEQ * OUTD + idx];
    __shared__ float red[9];
    int lane = t & 31, warp = t >> 5;
    float s = v;
#pragma unroll
    for (int o = 16; o; o >>= 1) s += __shfl_xor_sync(0xffffffffu, s, o);
    if (lane == 0) red[warp] = s;
    __syncthreads();
    if (t == 0) { float tot = 0; for (int i = 0; i < 8; i++) tot += red[i]; red[8] = tot; }
    __syncthreads();
    float mean = red[8] * (1.f / 256.f);
    float d = v - mean;
    float s2 = d * d;
#pragma unroll
    for (int o = 16; o; o >>= 1) s2 += __shfl_xor_sync(0xffffffffu, s2, o);
    __syncthreads();
    if (lane == 0) red[warp] = s2;
    __syncthreads();
    if (t == 0) { float tot = 0; for (int i = 0; i < 8; i++) tot += red[i]; red[8] = tot; }
    __syncthreads();
    float var = red[8] * (1.f / 256.f);
    out[idx] = d * rsqrtf(var + EPSV) * g[t] + b[t];
}

// ---------------- launch ---------------------------------------------------
extern "C" void kernel_launch(void* const* d_in, const int* in_sizes, int n_in,
                              void* d_out, int out_size)
{
    const float* forest = (const float*)d_in[0];
    const int*   perm   = (const int*)  d_in[2];
    const float* w_in   = (const float*)d_in[3];
    const float* b_in   = (const float*)d_in[4];
    const float* qkv_w  = (const float*)d_in[5];
    const float* qkv_b  = (const float*)d_in[6];
    const float* proj_w = (const float*)d_in[7];
    const float* proj_b = (const float*)d_in[8];
    const float* ff1_w  = (const float*)d_in[9];
    const float* ff1_b  = (const float*)d_in[10];
    const float* ff2_w  = (const float*)d_in[11];
    const float* ff2_b  = (const float*)d_in[12];
    const float* ln1_g  = (const float*)d_in[13];
    const float* ln1_b  = (const float*)d_in[14];
    const float* ln2_g  = (const float*)d_in[15];
    const float* ln2_b  = (const float*)d_in[16];
    const float* w_out  = (const float*)d_in[17];
    const float* b_out  = (const float*)d_in[18];
    const float* lnf_g  = (const float*)d_in[19];
    const float* lnf_b  = (const float*)d_in[20];

    float *xb, *ab, *pb;
    __half* qb;
    cudaGetSymbolAddress((void**)&xb, g_x);
    cudaGetSymbolAddress((void**)&qb, g_qkv);
    cudaGetSymbolAddress((void**)&ab, g_att);
    cudaGetSymbolAddress((void**)&pb, g_py);

    cudaFuncSetAttribute(qkv_kernel,
                         cudaFuncAttributeMaxDynamicSharedMemorySize, QKV_DYN_BYTES);
    cudaFuncSetAttribute(proj_kernel,
                         cudaFuncAttributeMaxDynamicSharedMemorySize, PROJ_DYN_BYTES);
    cudaFuncSetAttribute(ffn_kernel,
                         cudaFuncAttributeMaxDynamicSharedMemorySize, FFN_DYN_BYTES);
    cudaFuncSetAttribute(attn_mma_kernel,
                         cudaFuncAttributeMaxDynamicSharedMemorySize, ATTN_SMEM_BYTES);

    embed_kernel<<<MTOK / 16, 128>>>(forest, perm, w_in, b_in, xb);

    const int GR = MTOK / 128;  // 1936
    for (int l = 0; l < 2; l++) {
        qkv_kernel<<<GR, 256, QKV_DYN_BYTES>>>(
            xb, qkv_w + (size_t)l * 384 * 128, qkv_b + l * 384, qb);
        attn_mma_kernel<<<SEQ * NHEAD, 256, ATTN_SMEM_BYTES>>>(qb, ab);
        proj_kernel<<<GR, 256, PROJ_DYN_BYTES>>>(
            ab, proj_w + (size_t)l * 128 * 128, proj_b + l * 128,
            ln1_g + l * 128, ln1_b + l * 128, xb);
        ffn_kernel<<<GR, 256, FFN_DYN_BYTES>>>(
            xb, ff1_w + (size_t)l * 128 * 128, ff1_b + l * 128,
            ff2_w + (size_t)l * 128 * 128, ff2_b + l * 128,
            ln2_g + l * 128, ln2_b + l * 128, xb);
    }

    // output projection: split-K = 11 in one launch (15488 = 11 * 1408)
    gemm_splitk_kernel<<<dim3(OUTD / 128, SEQ / 128, SPLITK), 256>>>(
        xb, w_out, pb, SEQ, OUTD, KBIG, KBIG / SPLITK);
    out_ln_kernel<<<SEQ, 256>>>(pb, b_out, lnf_g, lnf_b, (float*)d_out);
}

// round 16
// speedup vs baseline: 1.1013x; 1.1013x over previous
#include <cuda_runtime.h>
#include <cuda_fp16.h>
#include <cstdint>

#define SEQ   2048          // B*A
#define NT    121           // tokens
#define HDIM  128           // hidden
#define FIND  12            // feature in
#define NHEAD 4
#define HDH   32            // head dim
#define OUTD  256
#define MTOK  (SEQ*NT)      // 247808
#define KBIG  (NT*HDIM)     // 15488
#define SPLITK 11
#define NSTG  3
#define NSTQ  4
#define STGF  (128 * 20)
#define EPSV  1e-5f

// ---------------- scratch (device globals; no allocation allowed) ----------
__device__ float  g_x  [(size_t)MTOK * HDIM];
__device__ __half g_qkv[(size_t)MTOK * 384];
__device__ float  g_att[(size_t)MTOK * HDIM];
__device__ float  g_py [(size_t)SPLITK * SEQ * OUTD];

__device__ __forceinline__ void cpasync16(uint32_t dst, const float* src) {
    asm volatile("cp.async.cg.shared.global [%0], [%1], 16;" :: "r"(dst), "l"(src));
}
__device__ __forceinline__ uint32_t smem_u32(const void* p) {
    uint32_t a;
    asm("{ .reg .u64 t; cvta.to.shared.u64 t, %1; cvt.u32.u64 %0, t; }" : "=r"(a) : "l"(p));
    return a;
}

__device__ __forceinline__ void mma_tf32(float c[4], uint32_t a0, uint32_t a1,
                                         uint32_t a2, uint32_t a3,
                                         uint32_t b0, uint32_t b1) {
    asm volatile(
        "mma.sync.aligned.m16n8k8.row.col.f32.tf32.tf32.f32 "
        "{%0,%1,%2,%3},{%4,%5,%6,%7},{%8,%9},{%0,%1,%2,%3};\n"
        : "+f"(c[0]), "+f"(c[1]), "+f"(c[2]), "+f"(c[3])
        : "r"(a0), "r"(a1), "r"(a2), "r"(a3), "r"(b0), "r"(b1));
}

// ---------------- embed: 16 tokens per CTA, 128 threads --------------------
__global__ void embed_kernel(const float* __restrict__ forest,
                             const int*   __restrict__ perm,
                             const float* __restrict__ w_in,
                             const float* __restrict__ b_in,
                             float* __restrict__ out)
{
    int t0 = blockIdx.x * 16;
    int h = threadIdx.x;               // 128
    float w[FIND];
#pragma unroll
    for (int k = 0; k < FIND; k++) w[k] = w_in[h * FIND + k];
    float bh = b_in[h];
#pragma unroll 1
    for (int j = 0; j < 16; j++) {
        int tok = t0 + j;
        int s = tok / NT, i = tok - s * NT;
        int node = __ldg(&perm[i]);
        const float* f = forest + ((size_t)s * NT + node) * FIND;
        float acc = bh;
#pragma unroll
        for (int k = 0; k < FIND; k++) acc += __ldg(&f[k]) * w[k];
        if (h < 12) {
            int mask = 0, cur = node;
            while (cur > 0) {
                int d = (cur >= 40) ? 4 : (cur >= 13) ? 3 : (cur >= 4) ? 2 : 1;
                int br = (cur - 1) % 3;
                mask |= 1 << ((d - 1) * 3 + br);
                cur = (cur - 1) / 3;
            }
            acc += (float)((mask >> h) & 1);
        }
        out[(size_t)tok * HDIM + h] = acc;
    }
}

// ============ TF32 tensor-core GEMM: C = X[M,K] @ W[Nc,K]^T + epilogue =====
// CTA 128x128, BK=16 x 3-stage cp.async pipeline.  (proven R9 config)
// mode 2: +bias+res, LayerNorm (Nc=128)   mode 3: raw partial store (split-K)
struct EpiSmem { float red[128][17]; float stat[128]; };
struct MmSmem  { float As[NSTG][128][20]; float Bs[NSTG][128][20]; };

__global__ __launch_bounds__(256, 2)
void gemm_tf32_kernel(const float* __restrict__ X, const float* __restrict__ W,
                      const float* __restrict__ bias, const float* __restrict__ res,
                      const float* __restrict__ lng, const float* __restrict__ lnb,
                      float* __restrict__ C, int M, int Nc, int K,
                      int kchunk, int mode)
{
    __shared__ union { MmSmem mm; EpiSmem ep; } sm;
    int tid = threadIdx.x;
    int lane = tid & 31, warp = tid >> 5;
    int tq = lane >> 2, tr = lane & 3;
    int warpM = warp & 1, warpN = warp >> 1;
    int row0 = blockIdx.y * 128, col0 = blockIdx.x * 128;
    int kstart = blockIdx.z * kchunk;
    if (mode == 3) C += (size_t)blockIdx.z * M * Nc;

    int glr = tid >> 1;
    int glc = (tid & 1) * 8;
    const float* Xp = X + (size_t)(row0 + glr) * K + kstart + glc;
    const float* Wp = W + (size_t)(col0 + glr) * K + kstart + glc;
    uint32_t sa = smem_u32(&sm.mm.As[0][glr][glc]);
    uint32_t sb = smem_u32(&sm.mm.Bs[0][glr][glc]);
    const uint32_t STGB = STGF * 4;

    int nk16 = kchunk >> 4;

#pragma unroll
    for (int s = 0; s < NSTG - 1; s++) {
        if (s < nk16) {
            uint32_t so = (uint32_t)s * STGB;
            const float* xp = Xp + s * 16;
            const float* wp = Wp + s * 16;
            cpasync16(sa + so, xp);       cpasync16(sa + so + 16, xp + 4);
            cpasync16(sb + so, wp);       cpasync16(sb + so + 16, wp + 4);
        }
        asm volatile("cp.async.commit_group;");
    }
    asm volatile("cp.async.wait_group %0;" :: "n"(NSTG - 2));
    __syncthreads();

    float acc[4][4][4] = {};
    uint32_t af[2][4][4], bf[2][4][2];
    int arow = warpM * 64 + tq;
    int brow = warpN * 32 + tq;

#pragma unroll
    for (int mi = 0; mi < 4; mi++) {
        af[0][mi][0] = __float_as_uint(sm.mm.As[0][arow + mi * 16    ][tr    ]);
        af[0][mi][1] = __float_as_uint(sm.mm.As[0][arow + mi * 16 + 8][tr    ]);
        af[0][mi][2] = __float_as_uint(sm.mm.As[0][arow + mi * 16    ][tr + 4]);
        af[0][mi][3] = __float_as_uint(sm.mm.As[0][arow + mi * 16 + 8][tr + 4]);
    }
#pragma unroll
    for (int ni = 0; ni < 4; ni++) {
        bf[0][ni][0] = __float_as_uint(sm.mm.Bs[0][brow + ni * 8][tr    ]);
        bf[0][ni][1] = __float_as_uint(sm.mm.Bs[0][brow + ni * 8][tr + 4]);
    }

    int buf = 0, wslot = NSTG - 1;
    for (int kt = 0; kt < nk16; kt++) {
#pragma unroll
        for (int mi = 0; mi < 4; mi++) {
            af[1][mi][0] = __float_as_uint(sm.mm.As[buf][arow + mi * 16    ][8 + tr    ]);
            af[1][mi][1] = __float_as_uint(sm.mm.As[buf][arow + mi * 16 + 8][8 + tr    ]);
            af[1][mi][2] = __float_as_uint(sm.mm.As[buf][arow + mi * 16    ][8 + tr + 4]);
            af[1][mi][3] = __float_as_uint(sm.mm.As[buf][arow + mi * 16 + 8][8 + tr + 4]);
        }
#pragma unroll
        for (int ni = 0; ni < 4; ni++) {
            bf[1][ni][0] = __float_as_uint(sm.mm.Bs[buf][brow + ni * 8][8 + tr    ]);
            bf[1][ni][1] = __float_as_uint(sm.mm.Bs[buf][brow + ni * 8][8 + tr + 4]);
        }
#pragma unroll
        for (int mi = 0; mi < 4; mi++)
#pragma unroll
            for (int ni = 0; ni < 4; ni++)
                mma_tf32(acc[mi][ni], af[0][mi][0], af[0][mi][1],
                         af[0][mi][2], af[0][mi][3],
                         bf[0][ni][0], bf[0][ni][1]);
        int snext = kt + NSTG - 1;
        if (snext < nk16) {
            uint32_t so = (uint32_t)wslot * STGB;
            const float* xp = Xp + snext * 16;
            const float* wp = Wp + snext * 16;
            cpasync16(sa + so, xp);       cpasync16(sa + so + 16, xp + 4);
            cpasync16(sb + so, wp);       cpasync16(sb + so + 16, wp + 4);
        }
        asm volatile("cp.async.commit_group;");
        asm volatile("cp.async.wait_group %0;" :: "n"(NSTG - 2));
        __syncthreads();
        if (++wslot == NSTG) wslot = 0;
        int nb = buf + 1; if (nb == NSTG) nb = 0;
        if (kt + 1 < nk16) {
#pragma unroll
            for (int mi = 0; mi < 4; mi++) {
                af[0][mi][0] = __float_as_uint(sm.mm.As[nb][arow + mi * 16    ][tr    ]);
                af[0][mi][1] = __float_as_uint(sm.mm.As[nb][arow + mi * 16 + 8][tr    ]);
                af[0][mi][2] = __float_as_uint(sm.mm.As[nb][arow + mi * 16    ][tr + 4]);
                af[0][mi][3] = __float_as_uint(sm.mm.As[nb][arow + mi * 16 + 8][tr + 4]);
            }
#pragma unroll
            for (int ni = 0; ni < 4; ni++) {
                bf[0][ni][0] = __float_as_uint(sm.mm.Bs[nb][brow + ni * 8][tr    ]);
                bf[0][ni][1] = __float_as_uint(sm.mm.Bs[nb][brow + ni * 8][tr + 4]);
            }
        }
#pragma unroll
        for (int mi = 0; mi < 4; mi++)
#pragma unroll
            for (int ni = 0; ni < 4; ni++)
                mma_tf32(acc[mi][ni], af[1][mi][0], af[1][mi][1],
                         af[1][mi][2], af[1][mi][3],
                         bf[1][ni][0], bf[1][ni][1]);
        buf = nb;
    }

    if (mode == 3) {
#pragma unroll
        for (int mi = 0; mi < 4; mi++)
#pragma unroll
            for (int h = 0; h < 2; h++) {
                int r = row0 + warpM * 64 + mi * 16 + tq + 8 * h;
#pragma unroll
                for (int ni = 0; ni < 4; ni++) {
                    int c = col0 + warpN * 32 + ni * 8 + 2 * tr;
                    *(float2*)&C[(size_t)r * Nc + c] =
                        make_float2(acc[mi][ni][2 * h], acc[mi][ni][2 * h + 1]);
                }
            }
        return;
    }

    // mode 2: bias + residual + LayerNorm over 128-wide rows (col0 == 0)
#pragma unroll
    for (int mi = 0; mi < 4; mi++)
#pragma unroll
        for (int h = 0; h < 2; h++) {
            int r = row0 + warpM * 64 + mi * 16 + tq + 8 * h;
#pragma unroll
            for (int ni = 0; ni < 4; ni++) {
                int c = warpN * 32 + ni * 8 + 2 * tr;
                float2 rv = *(const float2*)&res[(size_t)r * 128 + c];
                acc[mi][ni][2 * h]     += bias[c]     + rv.x;
                acc[mi][ni][2 * h + 1] += bias[c + 1] + rv.y;
            }
        }
    __syncthreads();
    int cid = warpN * 4 + tr;
#pragma unroll
    for (int mi = 0; mi < 4; mi++)
#pragma unroll
        for (int h = 0; h < 2; h++) {
            int rl = warpM * 64 + mi * 16 + tq + 8 * h;
            float s = 0.f;
#pragma unroll
            for (int ni = 0; ni < 4; ni++) s += acc[mi][ni][2 * h] + acc[mi][ni][2 * h + 1];
            sm.ep.red[rl][cid] = s;
        }
    __syncthreads();
    if (tid < 128) {
        float s = 0.f;
#pragma unroll
        for (int t = 0; t < 16; t++) s += sm.ep.red[tid][t];
        sm.ep.stat[tid] = s * (1.f / 128.f);
    }
    __syncthreads();
    float mean[4][2];
#pragma unroll
    for (int mi = 0; mi < 4; mi++)
#pragma unroll
        for (int h = 0; h < 2; h++)
            mean[mi][h] = sm.ep.stat[warpM * 64 + mi * 16 + tq + 8 * h];
    __syncthreads();
#pragma unroll
    for (int mi = 0; mi < 4; mi++)
#pragma unroll
        for (int h = 0; h < 2; h++) {
            int rl = warpM * 64 + mi * 16 + tq + 8 * h;
            float s = 0.f;
#pragma unroll
            for (int ni = 0; ni < 4; ni++) {
                float d0 = acc[mi][ni][2 * h]     - mean[mi][h];
                float d1 = acc[mi][ni][2 * h + 1] - mean[mi][h];
                s += d0 * d0 + d1 * d1;
            }
            sm.ep.red[rl][cid] = s;
        }
    __syncthreads();
    if (tid < 128) {
        float s = 0.f;
#pragma unroll
        for (int t = 0; t < 16; t++) s += sm.ep.red[tid][t];
        sm.ep.stat[tid] = rsqrtf(s * (1.f / 128.f) + EPSV);
    }
    __syncthreads();
#pragma unroll
    for (int mi = 0; mi < 4; mi++)
#pragma unroll
        for (int h = 0; h < 2; h++) {
            int rl = warpM * 64 + mi * 16 + tq + 8 * h;
            int r = row0 + rl;
            float rs = sm.ep.stat[rl];
#pragma unroll
            for (int ni = 0; ni < 4; ni++) {
                int c = warpN * 32 + ni * 8 + 2 * tr;
                float v0 = (acc[mi][ni][2 * h]     - mean[mi][h]) * rs * lng[c]     + lnb[c];
                float v1 = (acc[mi][ni][2 * h + 1] - mean[mi][h]) * rs * lng[c + 1] + lnb[c + 1];
                *(float2*)&C[(size_t)r * 128 + c] = make_float2(v0, v1);
            }
        }
}

// ========= QKV GEMM, smem-resident A, 4-stage B ring, half output ==========
#define QKV_DYN_BYTES (128 * 132 * 4 + NSTQ * STGF * 4)   // 67584 + 40960

__global__ __launch_bounds__(256, 2)
void qkv_kernel(const float* __restrict__ X, const float* __restrict__ W,
                const float* __restrict__ bias, __half* __restrict__ C)
{
    extern __shared__ float dsm[];
    float* Afull = dsm;                     // [128][132]
    float* BsR   = dsm + 128 * 132;         // [NSTQ][128][20]
#define QA(r, c)    Afull[(r) * 132 + (c)]
#define QB(s, r, c) BsR[(s) * STGF + (r) * 20 + (c)]

    int tid = threadIdx.x;
    int lane = tid & 31, warp = tid >> 5;
    int tq = lane >> 2, tr = lane & 3;
    int warpM = warp & 1, warpN = warp >> 1;
    int row0 = blockIdx.x * 128;

    uint32_t abase = smem_u32(&QA(0, 0));
    const float* Xb = X + (size_t)row0 * 128;
#pragma unroll
    for (int t = 0; t < 16; t++) {
        int m = tid + t * 256;
        int r = m >> 5, c4 = (m & 31) * 4;
        cpasync16(abase + (uint32_t)(r * 132 + c4) * 4, Xb + r * 128 + c4);
    }
    asm volatile("cp.async.commit_group;");

    int glr = tid >> 1, glc = (tid & 1) * 8;
    uint32_t sb = smem_u32(&QB(0, glr, glc));
    const uint32_t STGB = STGF * 4;

#pragma unroll
    for (int s = 0; s < 3; s++) {
        const float* wp = W + (size_t)glr * 128 + s * 16 + glc;
        cpasync16(sb + (uint32_t)s * STGB, wp);
        cpasync16(sb + (uint32_t)s * STGB + 16, wp + 4);
        asm volatile("cp.async.commit_group;");
    }
    asm volatile("cp.async.wait_group 2;");   // A + stage 0 complete
    __syncthreads();

    float acc[4][4][4] = {};
    uint32_t af[2][4][4], bf[2][4][2];
    int arow = warpM * 64 + tq;
    int brow = warpN * 32 + tq;

#pragma unroll
    for (int mi = 0; mi < 4; mi++) {
        af[0][mi][0] = __float_as_uint(QA(arow + mi * 16    , tr    ));
        af[0][mi][1] = __float_as_uint(QA(arow + mi * 16 + 8, tr    ));
        af[0][mi][2] = __float_as_uint(QA(arow + mi * 16    , tr + 4));
        af[0][mi][3] = __float_as_uint(QA(arow + mi * 16 + 8, tr + 4));
    }
#pragma unroll
    for (int ni = 0; ni < 4; ni++) {
        bf[0][ni][0] = __float_as_uint(QB(0, brow + ni * 8, tr    ));
        bf[0][ni][1] = __float_as_uint(QB(0, brow + ni * 8, tr + 4));
    }

    for (int g = 0; g < 24; g++) {
        int kt = g & 7;
        int buf = g & (NSTQ - 1);
        int kb = kt * 16;
#pragma unroll
        for (int mi = 0; mi < 4; mi++) {
            af[1][mi][0] = __float_as_uint(QA(arow + mi * 16    , kb + 8 + tr    ));
            af[1][mi][1] = __float_as_uint(QA(arow + mi * 16 + 8, kb + 8 + tr    ));
            af[1][mi][2] = __float_as_uint(QA(arow + mi * 16    , kb + 8 + tr + 4));
            af[1][mi][3] = __float_as_uint(QA(arow + mi * 16 + 8, kb + 8 + tr + 4));
        }
#pragma unroll
        for (int ni = 0; ni < 4; ni++) {
            bf[1][ni][0] = __float_as_uint(QB(buf, brow + ni * 8, 8 + tr    ));
            bf[1][ni][1] = __float_as_uint(QB(buf, brow + ni * 8, 8 + tr + 4));
        }
#pragma unroll
        for (int mi = 0; mi < 4; mi++)
#pragma unroll
            for (int ni = 0; ni < 4; ni++)
                mma_tf32(acc[mi][ni], af[0][mi][0], af[0][mi][1],
                         af[0][mi][2], af[0][mi][3],
                         bf[0][ni][0], bf[0][ni][1]);
        int gn = g + 3;
        if (gn < 24) {
            int ctn = gn >> 3, ktn = gn & 7;
            const float* wp = W + (size_t)(ctn * 128 + glr) * 128 + ktn * 16 + glc;
            uint32_t so = (uint32_t)(gn & (NSTQ - 1)) * STGB;
            cpasync16(sb + so, wp);   cpasync16(sb + so + 16, wp + 4);
        }
        asm volatile("cp.async.commit_group;");
        asm volatile("cp.async.wait_group 2;");
        __syncthreads();
        if (g + 1 < 24) {
            int k2 = ((g + 1) & 7) * 16;
            int b2 = (g + 1) & (NSTQ - 1);
#pragma unroll
            for (int mi = 0; mi < 4; mi++) {
                af[0][mi][0] = __float_as_uint(QA(arow + mi * 16    , k2 + tr    ));
                af[0][mi][1] = __float_as_uint(QA(arow + mi * 16 + 8, k2 + tr    ));
                af[0][mi][2] = __float_as_uint(QA(arow + mi * 16    , k2 + tr + 4));
                af[0][mi][3] = __float_as_uint(QA(arow + mi * 16 + 8, k2 + tr + 4));
            }
#pragma unroll
            for (int ni = 0; ni < 4; ni++) {
                bf[0][ni][0] = __float_as_uint(QB(b2, brow + ni * 8, tr    ));
                bf[0][ni][1] = __float_as_uint(QB(b2, brow + ni * 8, tr + 4));
            }
        }
#pragma unroll
        for (int mi = 0; mi < 4; mi++)
#pragma unroll
            for (int ni = 0; ni < 4; ni++)
                mma_tf32(acc[mi][ni], af[1][mi][0], af[1][mi][1],
                         af[1][mi][2], af[1][mi][3],
                         bf[1][ni][0], bf[1][ni][1]);
        if (kt == 7) {
            int cb = (g >> 3) * 128;
#pragma unroll
            for (int mi = 0; mi < 4; mi++)
#pragma unroll
                for (int h = 0; h < 2; h++) {
                    int r = row0 + warpM * 64 + mi * 16 + tq + 8 * h;
#pragma unroll
                    for (int ni = 0; ni < 4; ni++) {
                        int c = warpN * 32 + ni * 8 + 2 * tr;
                        float v0 = acc[mi][ni][2 * h]     + bias[cb + c];
                        float v1 = acc[mi][ni][2 * h + 1] + bias[cb + c + 1];
                        *(__half2*)&C[(size_t)r * 384 + cb + c] =
                            __floats2half2_rn(v0, v1);
                        acc[mi][ni][2 * h] = 0.f;
                        acc[mi][ni][2 * h + 1] = 0.f;
                    }
                }
        }
    }
#undef QA
#undef QB
}

// ======== tensor-core attention (half QKV in), one CTA per (seq, head) =====
// softmax: 256 threads (thread pair per row), float4 vectorized
#define ATTN_SMEM_FLOATS (128 * 132 + 32 * 132)
#define ATTN_SMEM_BYTES  (ATTN_SMEM_FLOATS * 4)

__global__ __launch_bounds__(256)
void attn_mma_kernel(const __half* __restrict__ qkv, float* __restrict__ out)
{
    extern __shared__ float smf[];
    float (*qs)[36]  = (float(*)[36])smf;
    float (*ks)[36]  = (float(*)[36])(smf + 128 * 36);
    float (*sp)[132] = (float(*)[132])smf;
    float (*vt)[132] = (float(*)[132])(smf + 128 * 132);

    int s  = blockIdx.x >> 2;
    int hh = blockIdx.x & 3;
    int tid = threadIdx.x;
    int lane = tid & 31, warp = tid >> 5;
    int tq = lane >> 2, tr = lane & 3;
    int warpM = warp & 1, warpN = warp >> 1;

    for (int idx = tid; idx < 7 * 36; idx += 256) {
        int r = 121 + idx / 36, c = idx % 36;
        qs[r][c] = 0.f;
        ks[r][c] = 0.f;
    }
    for (int idx = tid; idx < 32 * 7; idx += 256) {
        int d = idx / 7, c = 121 + idx % 7;
        vt[d][c] = 0.f;
    }

    const __half* base = qkv + (size_t)s * NT * 384 + hh * HDH;
    for (int idx = tid; idx < NT * 8; idx += 256) {
        int n = idx >> 3, d4 = (idx & 7) * 4;
        const __half* bp = base + (size_t)n * 384 + d4;
        float2 q01 = __half22float2(*(const __half2*)(bp));
        float2 q23 = __half22float2(*(const __half2*)(bp + 2));
        float2 k01 = __half22float2(*(const __half2*)(bp + 128));
        float2 k23 = __half22float2(*(const __half2*)(bp + 130));
        float2 v01 = __half22float2(*(const __half2*)(bp + 256));
        float2 v23 = __half22float2(*(const __half2*)(bp + 258));
        qs[n][d4 + 0] = q01.x; qs[n][d4 + 1] = q01.y;
        qs[n][d4 + 2] = q23.x; qs[n][d4 + 3] = q23.y;
        ks[n][d4 + 0] = k01.x; ks[n][d4 + 1] = k01.y;
        ks[n][d4 + 2] = k23.x; ks[n][d4 + 3] = k23.y;
        vt[d4 + 0][n] = v01.x;
        vt[d4 + 1][n] = v01.y;
        vt[d4 + 2][n] = v23.x;
        vt[d4 + 3][n] = v23.y;
    }
    __syncthreads();

    float acc[4][4][4] = {};
#pragma unroll
    for (int k8 = 0; k8 < 32; k8 += 8) {
        uint32_t af[4][4], bf[4][2];
#pragma unroll
        for (int mi = 0; mi < 4; mi++) {
            int ar = warpM * 64 + mi * 16 + tq;
            af[mi][0] = __float_as_uint(qs[ar    ][k8 + tr    ]);
            af[mi][1] = __float_as_uint(qs[ar + 8][k8 + tr    ]);
            af[mi][2] = __float_as_uint(qs[ar    ][k8 + tr + 4]);
            af[mi][3] = __float_as_uint(qs[ar + 8][k8 + tr + 4]);
        }
#pragma unroll
        for (int ni = 0; ni < 4; ni++) {
            int br = warpN * 32 + ni * 8 + tq;
            bf[ni][0] = __float_as_uint(ks[br][k8 + tr    ]);
            bf[ni][1] = __float_as_uint(ks[br][k8 + tr + 4]);
        }
#pragma unroll
        for (int mi = 0; mi < 4; mi++)
#pragma unroll
            for (int ni = 0; ni < 4; ni++)
                mma_tf32(acc[mi][ni], af[mi][0], af[mi][1], af[mi][2], af[mi][3],
                         bf[ni][0], bf[ni][1]);
    }
    __syncthreads();

#pragma unroll
    for (int mi = 0; mi < 4; mi++)
#pragma unroll
        for (int h = 0; h < 2; h++) {
            int r = warpM * 64 + mi * 16 + tq + 8 * h;
#pragma unroll
            for (int ni = 0; ni < 4; ni++) {
                int c = warpN * 32 + ni * 8 + 2 * tr;
                *(float2*)&sp[r][c] = make_float2(acc[mi][ni][2 * h], acc[mi][ni][2 * h + 1]);
            }
        }
    __syncthreads();

    // ---- softmax: thread pair per row; halves combined via shfl_xor(1) ----
    const float scale = 0.17677669529663687f;
    {
        int r2 = tid >> 1, hf = tid & 1;
        float* row = &sp[r2][0];
        float4* rowq = (float4*)(row + hf * 64);
        int nq = hf ? 14 : 16;               // half0: cols 0..63; half1: 64..119
        float mx = hf ? row[120] : -1e30f;   // col 120 handled by half1
        for (int q = 0; q < nq; q++) {
            float4 v = rowq[q];
            mx = fmaxf(mx, fmaxf(fmaxf(v.x, v.y), fmaxf(v.z, v.w)));
        }
        mx = fmaxf(mx, __shfl_xor_sync(0xffffffffu, mx, 1));
        float sum = 0.f;
        for (int q = 0; q < nq; q++) {
            float4 v = rowq[q];
            v.x = __expf((v.x - mx) * scale);
            v.y = __expf((v.y - mx) * scale);
            v.z = __expf((v.z - mx) * scale);
            v.w = __expf((v.w - mx) * scale);
            rowq[q] = v;
            sum += v.x + v.y + v.z + v.w;
        }
        if (hf) {
            float e = __expf((row[120] - mx) * scale);
            row[120] = e;
            sum += e;
        }
        sum += __shfl_xor_sync(0xffffffffu, sum, 1);
        float inv = 1.f / sum;
        for (int q = 0; q < nq; q++) {
            float4 v = rowq[q];
            v.x *= inv; v.y *= inv; v.z *= inv; v.w *= inv;
            rowq[q] = v;
        }
        if (hf) {
            row[120] *= inv;
#pragma unroll
            for (int c = NT; c < 128; c++) row[c] = 0.f;
        }
    }
    __syncthreads();

    float pacc[4][4] = {};
#pragma unroll
    for (int k8 = 0; k8 < 128; k8 += 8) {
        uint32_t af[4][4], bf[2];
#pragma unroll
        for (int mi = 0; mi < 4; mi++) {
            int ar = warpM * 64 + mi * 16 + tq;
            af[mi][0] = __float_as_uint(sp[ar    ][k8 + tr    ]);
            af[mi][1] = __float_as_uint(sp[ar + 8][k8 + tr    ]);
            af[mi][2] = __float_as_uint(sp[ar    ][k8 + tr + 4]);
            af[mi][3] = __float_as_uint(sp[ar + 8][k8 + tr + 4]);
        }
        int bn = warpN * 8 + tq;
        bf[0] = __float_as_uint(vt[bn][k8 + tr    ]);
        bf[1] = __float_as_uint(vt[bn][k8 + tr + 4]);
#pragma unroll
        for (int mi = 0; mi < 4; mi++)
            mma_tf32(pacc[mi], af[mi][0], af[mi][1], af[mi][2], af[mi][3],
                     bf[0], bf[1]);
    }

#pragma unroll
    for (int mi = 0; mi < 4; mi++)
#pragma unroll
        for (int h = 0; h < 2; h++) {
            int r = warpM * 64 + mi * 16 + tq + 8 * h;
            if (r < NT) {
                int c = warpN * 8 + 2 * tr;
                *(float2*)&out[((size_t)s * NT + r) * HDIM + hh * HDH + c] =
                    make_float2(pacc[mi][2 * h], pacc[mi][2 * h + 1]);
            }
        }
}

// ========== fused FFN: x = LN(x + relu(x@W1^T+b1)@W2^T + b2) ==============
#define FFN_DYN_BYTES (NSTG * STGF * 4 + 128 * 132 * 4)   // 30720 + 67584

__global__ __launch_bounds__(256, 2)
void ffn_kernel(const float* __restrict__ X,
                const float* __restrict__ W1, const float* __restrict__ b1,
                const float* __restrict__ W2, const float* __restrict__ b2,
                const float* __restrict__ lng, const float* __restrict__ lnb,
                float* __restrict__ C)
{
    extern __shared__ float dsm[];
    float* BsR = dsm;
    float* AR  = dsm + NSTG * STGF;
#define FB(s, r, c) BsR[(s) * STGF + (r) * 20 + (c)]
#define FA(s, r, c) AR[(s) * STGF + (r) * 20 + (c)]
#define HS(r, c)    AR[(r) * 132 + (c)]

    int tid = threadIdx.x;
    int lane = tid & 31, warp = tid >> 5;
    int tq = lane >> 2, tr = lane & 3;
    int warpM = warp & 1, warpN = warp >> 1;
    int row0 = blockIdx.x * 128;

    int glr = tid >> 1;
    int glc = (tid & 1) * 8;
    const float* Xp  = X  + (size_t)(row0 + glr) * 128 + glc;
    const float* W1p = W1 + (size_t)glr * 128 + glc;
    const float* W2p = W2 + (size_t)glr * 128 + glc;
    uint32_t sa = smem_u32(&FA(0, glr, glc));
    uint32_t sb = smem_u32(&FB(0, glr, glc));
    const uint32_t STGB = STGF * 4;

    int arow = warpM * 64 + tq;
    int brow = warpN * 32 + tq;
    float acc[4][4][4] = {};
    uint32_t af[2][4][4], bf[2][4][2];

#pragma unroll
    for (int s = 0; s < NSTG - 1; s++) {
        uint32_t so = (uint32_t)s * STGB;
        cpasync16(sa + so, Xp + s * 16);       cpasync16(sa + so + 16, Xp + s * 16 + 4);
        cpasync16(sb + so, W1p + s * 16);      cpasync16(sb + so + 16, W1p + s * 16 + 4);
        asm volatile("cp.async.commit_group;");
    }
    asm volatile("cp.async.wait_group %0;" :: "n"(NSTG - 2));
    __syncthreads();

#pragma unroll
    for (int mi = 0; mi < 4; mi++) {
        af[0][mi][0] = __float_as_uint(FA(0, arow + mi * 16    , tr    ));
        af[0][mi][1] = __float_as_uint(FA(0, arow + mi * 16 + 8, tr    ));
        af[0][mi][2] = __float_as_uint(FA(0, arow + mi * 16    , tr + 4));
        af[0][mi][3] = __float_as_uint(FA(0, arow + mi * 16 + 8, tr + 4));
    }
#pragma unroll
    for (int ni = 0; ni < 4; ni++) {
        bf[0][ni][0] = __float_as_uint(FB(0, brow + ni * 8, tr    ));
        bf[0][ni][1] = __float_as_uint(FB(0, brow + ni * 8, tr + 4));
    }

    int buf = 0, wslot = NSTG - 1;
    for (int kt = 0; kt < 8; kt++) {
#pragma unroll
        for (int mi = 0; mi < 4; mi++) {
            af[1][mi][0] = __float_as_uint(FA(buf, arow + mi * 16    , 8 + tr    ));
            af[1][mi][1] = __float_as_uint(FA(buf, arow + mi * 16 + 8, 8 + tr    ));
            af[1][mi][2] = __float_as_uint(FA(buf, arow + mi * 16    , 8 + tr + 4));
            af[1][mi][3] = __float_as_uint(FA(buf, arow + mi * 16 + 8, 8 + tr + 4));
        }
#pragma unroll
        for (int ni = 0; ni < 4; ni++) {
            bf[1][ni][0] = __float_as_uint(FB(buf, brow + ni * 8, 8 + tr    ));
            bf[1][ni][1] = __float_as_uint(FB(buf, brow + ni * 8, 8 + tr + 4));
        }
#pragma unroll
        for (int mi = 0; mi < 4; mi++)
#pragma unroll
            for (int ni = 0; ni < 4; ni++)
                mma_tf32(acc[mi][ni], af[0][mi][0], af[0][mi][1],
                         af[0][mi][2], af[0][mi][3],
                         bf[0][ni][0], bf[0][ni][1]);
        int snext = kt + NSTG - 1;
        if (snext < 8) {
            uint32_t so = (uint32_t)wslot * STGB;
            cpasync16(sa + so, Xp + snext * 16);   cpasync16(sa + so + 16, Xp + snext * 16 + 4);
            cpasync16(sb + so, W1p + snext * 16);  cpasync16(sb + so + 16, W1p + snext * 16 + 4);
        }
        asm volatile("cp.async.commit_group;");
        asm volatile("cp.async.wait_group %0;" :: "n"(NSTG - 2));
        __syncthreads();
        if (++wslot == NSTG) wslot = 0;
        int nb = buf + 1; if (nb == NSTG) nb = 0;
        if (kt + 1 < 8) {
#pragma unroll
            for (int mi = 0; mi < 4; mi++) {
                af[0][mi][0] = __float_as_uint(FA(nb, arow + mi * 16    , tr    ));
                af[0][mi][1] = __float_as_uint(FA(nb, arow + mi * 16 + 8, tr    ));
                af[0][mi][2] = __float_as_uint(FA(nb, arow + mi * 16    , tr + 4));
                af[0][mi][3] = __float_as_uint(FA(nb, arow + mi * 16 + 8, tr + 4));
            }
#pragma unroll
            for (int ni = 0; ni < 4; ni++) {
                bf[0][ni][0] = __float_as_uint(FB(nb, brow + ni * 8, tr    ));
                bf[0][ni][1] = __float_as_uint(FB(nb, brow + ni * 8, tr + 4));
            }
        }
#pragma unroll
        for (int mi = 0; mi < 4; mi++)
#pragma unroll
            for (int ni = 0; ni < 4; ni++)
                mma_tf32(acc[mi][ni], af[1][mi][0], af[1][mi][1],
                         af[1][mi][2], af[1][mi][3],
                         bf[1][ni][0], bf[1][ni][1]);
        buf = nb;
    }

#pragma unroll
    for (int s = 0; s < NSTG - 1; s++) {
        uint32_t so = (uint32_t)s * STGB;
        cpasync16(sb + so, W2p + s * 16);      cpasync16(sb + so + 16, W2p + s * 16 + 4);
        asm volatile("cp.async.commit_group;");
    }

#pragma unroll
    for (int mi = 0; mi < 4; mi++)
#pragma unroll
        for (int h2 = 0; h2 < 2; h2++) {
            int r = warpM * 64 + mi * 16 + tq + 8 * h2;
#pragma unroll
            for (int ni = 0; ni < 4; ni++) {
                int c = warpN * 32 + ni * 8 + 2 * tr;
                HS(r, c)     = fmaxf(acc[mi][ni][2 * h2]     + b1[c],     0.f);
                HS(r, c + 1) = fmaxf(acc[mi][ni][2 * h2 + 1] + b1[c + 1], 0.f);
            }
        }
    asm volatile("cp.async.wait_group %0;" :: "n"(NSTG - 2));
    __syncthreads();

#pragma unroll
    for (int mi = 0; mi < 4; mi++)
#pragma unroll
        for (int ni = 0; ni < 4; ni++)
#pragma unroll
            for (int q = 0; q < 4; q++) acc[mi][ni][q] = 0.f;

#pragma unroll
    for (int mi = 0; mi < 4; mi++) {
        af[0][mi][0] = __float_as_uint(HS(arow + mi * 16    , tr    ));
        af[0][mi][1] = __float_as_uint(HS(arow + mi * 16 + 8, tr    ));
        af[0][mi][2] = __float_as_uint(HS(arow + mi * 16    , tr + 4));
        af[0][mi][3] = __float_as_uint(HS(arow + mi * 16 + 8, tr + 4));
    }
#pragma unroll
    for (int ni = 0; ni < 4; ni++) {
        bf[0][ni][0] = __float_as_uint(FB(0, brow + ni * 8, tr    ));
        bf[0][ni][1] = __float_as_uint(FB(0, brow + ni * 8, tr + 4));
    }

    buf = 0; wslot = NSTG - 1;
    for (int kt = 0; kt < 8; kt++) {
        int kb = kt * 16;
#pragma unroll
        for (int mi = 0; mi < 4; mi++) {
            af[1][mi][0] = __float_as_uint(HS(arow + mi * 16    , kb + 8 + tr    ));
            af[1][mi][1] = __float_as_uint(HS(arow + mi * 16 + 8, kb + 8 + tr    ));
            af[1][mi][2] = __float_as_uint(HS(arow + mi * 16    , kb + 8 + tr + 4));
            af[1][mi][3] = __float_as_uint(HS(arow + mi * 16 + 8, kb + 8 + tr + 4));
        }
#pragma unroll
        for (int ni = 0; ni < 4; ni++) {
            bf[1][ni][0] = __float_as_uint(FB(buf, brow + ni * 8, 8 + tr    ));
            bf[1][ni][1] = __float_as_uint(FB(buf, brow + ni * 8, 8 + tr + 4));
        }
#pragma unroll
        for (int mi = 0; mi < 4; mi++)
#pragma unroll
            for (int ni = 0; ni < 4; ni++)
                mma_tf32(acc[mi][ni], af[0][mi][0], af[0][mi][1],
                         af[0][mi][2], af[0][mi][3],
                         bf[0][ni][0], bf[0][ni][1]);
        int snext = kt + NSTG - 1;
        if (snext < 8) {
            uint32_t so = (uint32_t)wslot * STGB;
            cpasync16(sb + so, W2p + snext * 16);  cpasync16(sb + so + 16, W2p + snext * 16 + 4);
        }
        asm volatile("cp.async.commit_group;");
        asm volatile("cp.async.wait_group %0;" :: "n"(NSTG - 2));
        __syncthreads();
        if (++wslot == NSTG) wslot = 0;
        int nb = buf + 1; if (nb == NSTG) nb = 0;
        if (kt + 1 < 8) {
            int kn = (kt + 1) * 16;
#pragma unroll
            for (int mi = 0; mi < 4; mi++) {
                af[0][mi][0] = __float_as_uint(HS(arow + mi * 16    , kn + tr    ));
                af[0][mi][1] = __float_as_uint(HS(arow + mi * 16 + 8, kn + tr    ));
                af[0][mi][2] = __float_as_uint(HS(arow + mi * 16    , kn + tr + 4));
                af[0][mi][3] = __float_as_uint(HS(arow + mi * 16 + 8, kn + tr + 4));
            }
#pragma unroll
            for (int ni = 0; ni < 4; ni++) {
                bf[0][ni][0] = __float_as_uint(FB(nb, brow + ni * 8, tr    ));
                bf[0][ni][1] = __float_as_uint(FB(nb, brow + ni * 8, tr + 4));
            }
        }
#pragma unroll
        for (int mi = 0; mi < 4; mi++)
#pragma unroll
            for (int ni = 0; ni < 4; ni++)
                mma_tf32(acc[mi][ni], af[1][mi][0], af[1][mi][1],
                         af[1][mi][2], af[1][mi][3],
                         bf[1][ni][0], bf[1][ni][1]);
        buf = nb;
    }

    float* red  = dsm;
    float* stat = dsm + 128 * 17;
#pragma unroll
    for (int mi = 0; mi < 4; mi++)
#pragma unroll
        for (int h2 = 0; h2 < 2; h2++) {
            int r = row0 + warpM * 64 + mi * 16 + tq + 8 * h2;
#pragma unroll
            for (int ni = 0; ni < 4; ni++) {
                int c = warpN * 32 + ni * 8 + 2 * tr;
                float2 rv = *(const float2*)&X[(size_t)r * 128 + c];
                acc[mi][ni][2 * h2]     += b2[c]     + rv.x;
                acc[mi][ni][2 * h2 + 1] += b2[c + 1] + rv.y;
            }
        }
    __syncthreads();
    int cid = warpN * 4 + tr;
#pragma unroll
    for (int mi = 0; mi < 4; mi++)
#pragma unroll
        for (int h2 = 0; h2 < 2; h2++) {
            int rl = warpM * 64 + mi * 16 + tq + 8 * h2;
            float s = 0.f;
#pragma unroll
            for (int ni = 0; ni < 4; ni++) s += acc[mi][ni][2 * h2] + acc[mi][ni][2 * h2 + 1];
            red[rl * 17 + cid] = s;
        }
    __syncthreads();
    if (tid < 128) {
        float s = 0.f;
#pragma unroll
        for (int t = 0; t < 16; t++) s += red[tid * 17 + t];
        stat[tid] = s * (1.f / 128.f);
    }
    __syncthreads();
    float mean[4][2];
#pragma unroll
    for (int mi = 0; mi < 4; mi++)
#pragma unroll
        for (int h2 = 0; h2 < 2; h2++)
            mean[mi][h2] = stat[warpM * 64 + mi * 16 + tq + 8 * h2];
    __syncthreads();
#pragma unroll
    for (int mi = 0; mi < 4; mi++)
#pragma unroll
        for (int h2 = 0; h2 < 2; h2++) {
            int rl = warpM * 64 + mi * 16 + tq + 8 * h2;
            float s = 0.f;
#pragma unroll
            for (int ni = 0; ni < 4; ni++) {
                float d0 = acc[mi][ni][2 * h2]     - mean[mi][h2];
                float d1 = acc[mi][ni][2 * h2 + 1] - mean[mi][h2];
                s += d0 * d0 + d1 * d1;
            }
            red[rl * 17 + cid] = s;
        }
    __syncthreads();
    if (tid < 128) {
        float s = 0.f;
#pragma unroll
        for (int t = 0; t < 16; t++) s += red[tid * 17 + t];
        stat[tid] = rsqrtf(s * (1.f / 128.f) + EPSV);
    }
    __syncthreads();
#pragma unroll
    for (int mi = 0; mi < 4; mi++)
#pragma unroll
        for (int h2 = 0; h2 < 2; h2++) {
            int rl = warpM * 64 + mi * 16 + tq + 8 * h2;
            int r = row0 + rl;
            float rs = stat[rl];
#pragma unroll
            for (int ni = 0; ni < 4; ni++) {
                int c = warpN * 32 + ni * 8 + 2 * tr;
                float v0 = (acc[mi][ni][2 * h2]     - mean[mi][h2]) * rs * lng[c]     + lnb[c];
                float v1 = (acc[mi][ni][2 * h2 + 1] - mean[mi][h2]) * rs * lng[c + 1] + lnb[c + 1];
                *(float2*)&C[(size_t)r * 128 + c] = make_float2(v0, v1);
            }
        }
#undef FB
#undef FA
#undef HS
}

// ------- final: reduce split-K partials + bias + LayerNorm over 256 -------
__global__ void out_ln_kernel(const float* __restrict__ part,
                              const float* __restrict__ b_out,
                              const float* __restrict__ g,
                              const float* __restrict__ b,
                              float* __restrict__ out)
{
    int row = blockIdx.x, t = threadIdx.x;
    size_t idx = (size_t)row * OUTD + t;
    float v = b_out[t];
#pragma unroll
    for (int z = 0; z < SPLITK; z++) v += part[(size_t)z * SEQ * OUTD + idx];
    __shared__ float red[9];
    int lane = t & 31, warp = t >> 5;
    float s = v;
#pragma unroll
    for (int o = 16; o; o >>= 1) s += __shfl_xor_sync(0xffffffffu, s, o);
    if (lane == 0) red[warp] = s;
    __syncthreads();
    if (t == 0) { float tot = 0; for (int i = 0; i < 8; i++) tot += red[i]; red[8] = tot; }
    __syncthreads();
    float mean = red[8] * (1.f / 256.f);
    float d = v - mean;
    float s2 = d * d;
#pragma unroll
    for (int o = 16; o; o >>= 1) s2 += __shfl_xor_sync(0xffffffffu, s2, o);
    __syncthreads();
    if (lane == 0) red[warp] = s2;
    __syncthreads();
    if (t == 0) { float tot = 0; for (int i = 0; i < 8; i++) tot += red[i]; red[8] = tot; }
    __syncthreads();
    float var = red[8] * (1.f / 256.f);
    out[idx] = d * rsqrtf(var + EPSV) * g[t] + b[t];
}

// ---------------- launch ---------------------------------------------------
extern "C" void kernel_launch(void* const* d_in, const int* in_sizes, int n_in,
                              void* d_out, int out_size)
{
    const float* forest = (const float*)d_in[0];
    const int*   perm   = (const int*)  d_in[2];
    const float* w_in   = (const float*)d_in[3];
    const float* b_in   = (const float*)d_in[4];
    const float* qkv_w  = (const float*)d_in[5];
    const float* qkv_b  = (const float*)d_in[6];
    const float* proj_w = (const float*)d_in[7];
    const float* proj_b = (const float*)d_in[8];
    const float* ff1_w  = (const float*)d_in[9];
    const float* ff1_b  = (const float*)d_in[10];
    const float* ff2_w  = (const float*)d_in[11];
    const float* ff2_b  = (const float*)d_in[12];
    const float* ln1_g  = (const float*)d_in[13];
    const float* ln1_b  = (const float*)d_in[14];
    const float* ln2_g  = (const float*)d_in[15];
    const float* ln2_b  = (const float*)d_in[16];
    const float* w_out  = (const float*)d_in[17];
    const float* b_out  = (const float*)d_in[18];
    const float* lnf_g  = (const float*)d_in[19];
    const float* lnf_b  = (const float*)d_in[20];

    float *xb, *ab, *pb;
    __half* qb;
    cudaGetSymbolAddress((void**)&xb, g_x);
    cudaGetSymbolAddress((void**)&qb, g_qkv);
    cudaGetSymbolAddress((void**)&ab, g_att);
    cudaGetSymbolAddress((void**)&pb, g_py);

    cudaFuncSetAttribute(qkv_kernel,
                         cudaFuncAttributeMaxDynamicSharedMemorySize, QKV_DYN_BYTES);
    cudaFuncSetAttribute(ffn_kernel,
                         cudaFuncAttributeMaxDynamicSharedMemorySize, FFN_DYN_BYTES);
    cudaFuncSetAttribute(attn_mma_kernel,
                         cudaFuncAttributeMaxDynamicSharedMemorySize, ATTN_SMEM_BYTES);

    embed_kernel<<<MTOK / 16, 128>>>(forest, perm, w_in, b_in, xb);

    const int GR = MTOK / 128;  // 1936
    for (int l = 0; l < 2; l++) {
        qkv_kernel<<<GR, 256, QKV_DYN_BYTES>>>(
            xb, qkv_w + (size_t)l * 384 * 128, qkv_b + l * 384, qb);
        attn_mma_kernel<<<SEQ * NHEAD, 256, ATTN_SMEM_BYTES>>>(qb, ab);
        gemm_tf32_kernel<<<dim3(1, GR), 256>>>(
            ab, proj_w + (size_t)l * 128 * 128, proj_b + l * 128,
            xb, ln1_g + l * 128, ln1_b + l * 128, xb, MTOK, 128, 128, 128, 2);
        ffn_kernel<<<GR, 256, FFN_DYN_BYTES>>>(
            xb, ff1_w + (size_t)l * 128 * 128, ff1_b + l * 128,
            ff2_w + (size_t)l * 128 * 128, ff2_b + l * 128,
            ln2_g + l * 128, ln2_b + l * 128, xb);
    }

    // output projection: split-K = 11 in one launch (15488 = 11 * 1408)
    gemm_tf32_kernel<<<dim3(OUTD / 128, SEQ / 128, SPLITK), 256>>>(
        xb, w_out, nullptr, nullptr, nullptr, nullptr,
        pb, SEQ, OUTD, KBIG, KBIG / SPLITK, 3);
    out_ln_kernel<<<SEQ, 256>>>(pb, b_out, lnf_g, lnf_b, (float*)d_out);
}

// round 17
// speedup vs baseline: 1.1643x; 1.0572x over previous
#include <cuda_runtime.h>
#include <cuda_fp16.h>
#include <cstdint>

#define SEQ   2048          // B*A
#define NT    121           // tokens
#define HDIM  128           // hidden
#define FIND  12            // feature in
#define NHEAD 4
#define HDH   32            // head dim
#define OUTD  256
#define MTOK  (SEQ*NT)      // 247808
#define KBIG  (NT*HDIM)     // 15488
#define SPLITK 11
#define NSTG  3
#define NSTQ  4
#define STGF  (128 * 20)
#define EPSV  1e-5f

// ---------------- scratch (device globals; no allocation allowed) ----------
__device__ float  g_x  [(size_t)MTOK * HDIM];
__device__ __half g_qkv[(size_t)MTOK * 384];
__device__ float  g_att[(size_t)MTOK * HDIM];
__device__ float  g_py [(size_t)SPLITK * SEQ * OUTD];

__device__ __forceinline__ void cpasync16(uint32_t dst, const float* src) {
    asm volatile("cp.async.cg.shared.global [%0], [%1], 16;" :: "r"(dst), "l"(src));
}
__device__ __forceinline__ uint32_t smem_u32(const void* p) {
    uint32_t a;
    asm("{ .reg .u64 t; cvta.to.shared.u64 t, %1; cvt.u32.u64 %0, t; }" : "=r"(a) : "l"(p));
    return a;
}

__device__ __forceinline__ void mma_tf32(float c[4], uint32_t a0, uint32_t a1,
                                         uint32_t a2, uint32_t a3,
                                         uint32_t b0, uint32_t b1) {
    asm volatile(
        "mma.sync.aligned.m16n8k8.row.col.f32.tf32.tf32.f32 "
        "{%0,%1,%2,%3},{%4,%5,%6,%7},{%8,%9},{%0,%1,%2,%3};\n"
        : "+f"(c[0]), "+f"(c[1]), "+f"(c[2]), "+f"(c[3])
        : "r"(a0), "r"(a1), "r"(a2), "r"(a3), "r"(b0), "r"(b1));
}

__device__ __forceinline__ void mma_f16(float c[4], uint32_t a0, uint32_t a1,
                                        uint32_t a2, uint32_t a3,
                                        uint32_t b0, uint32_t b1) {
    asm volatile(
        "mma.sync.aligned.m16n8k16.row.col.f32.f16.f16.f32 "
        "{%0,%1,%2,%3},{%4,%5,%6,%7},{%8,%9},{%0,%1,%2,%3};\n"
        : "+f"(c[0]), "+f"(c[1]), "+f"(c[2]), "+f"(c[3])
        : "r"(a0), "r"(a1), "r"(a2), "r"(a3), "r"(b0), "r"(b1));
}

// ---------------- embed: 16 tokens per CTA, 128 threads --------------------
__global__ void embed_kernel(const float* __restrict__ forest,
                             const int*   __restrict__ perm,
                             const float* __restrict__ w_in,
                             const float* __restrict__ b_in,
                             float* __restrict__ out)
{
    int t0 = blockIdx.x * 16;
    int h = threadIdx.x;               // 128
    float w[FIND];
#pragma unroll
    for (int k = 0; k < FIND; k++) w[k] = w_in[h * FIND + k];
    float bh = b_in[h];
#pragma unroll 1
    for (int j = 0; j < 16; j++) {
        int tok = t0 + j;
        int s = tok / NT, i = tok - s * NT;
        int node = __ldg(&perm[i]);
        const float* f = forest + ((size_t)s * NT + node) * FIND;
        float acc = bh;
#pragma unroll
        for (int k = 0; k < FIND; k++) acc += __ldg(&f[k]) * w[k];
        if (h < 12) {
            int mask = 0, cur = node;
            while (cur > 0) {
                int d = (cur >= 40) ? 4 : (cur >= 13) ? 3 : (cur >= 4) ? 2 : 1;
                int br = (cur - 1) % 3;
                mask |= 1 << ((d - 1) * 3 + br);
                cur = (cur - 1) / 3;
            }
            acc += (float)((mask >> h) & 1);
        }
        out[(size_t)tok * HDIM + h] = acc;
    }
}

// ============ TF32 tensor-core GEMM: C = X[M,K] @ W[Nc,K]^T + epilogue =====
// mode 2: +bias+res, LayerNorm (Nc=128)   mode 3: raw partial store (split-K)
struct EpiSmem { float red[128][17]; float stat[128]; };
struct MmSmem  { float As[NSTG][128][20]; float Bs[NSTG][128][20]; };

__global__ __launch_bounds__(256, 2)
void gemm_tf32_kernel(const float* __restrict__ X, const float* __restrict__ W,
                      const float* __restrict__ bias, const float* __restrict__ res,
                      const float* __restrict__ lng, const float* __restrict__ lnb,
                      float* __restrict__ C, int M, int Nc, int K,
                      int kchunk, int mode)
{
    __shared__ union { MmSmem mm; EpiSmem ep; } sm;
    int tid = threadIdx.x;
    int lane = tid & 31, warp = tid >> 5;
    int tq = lane >> 2, tr = lane & 3;
    int warpM = warp & 1, warpN = warp >> 1;
    int row0 = blockIdx.y * 128, col0 = blockIdx.x * 128;
    int kstart = blockIdx.z * kchunk;
    if (mode == 3) C += (size_t)blockIdx.z * M * Nc;

    int glr = tid >> 1;
    int glc = (tid & 1) * 8;
    const float* Xp = X + (size_t)(row0 + glr) * K + kstart + glc;
    const float* Wp = W + (size_t)(col0 + glr) * K + kstart + glc;
    uint32_t sa = smem_u32(&sm.mm.As[0][glr][glc]);
    uint32_t sb = smem_u32(&sm.mm.Bs[0][glr][glc]);
    const uint32_t STGB = STGF * 4;

    int nk16 = kchunk >> 4;

#pragma unroll
    for (int s = 0; s < NSTG - 1; s++) {
        if (s < nk16) {
            uint32_t so = (uint32_t)s * STGB;
            const float* xp = Xp + s * 16;
            const float* wp = Wp + s * 16;
            cpasync16(sa + so, xp);       cpasync16(sa + so + 16, xp + 4);
            cpasync16(sb + so, wp);       cpasync16(sb + so + 16, wp + 4);
        }
        asm volatile("cp.async.commit_group;");
    }
    asm volatile("cp.async.wait_group %0;" :: "n"(NSTG - 2));
    __syncthreads();

    float acc[4][4][4] = {};
    uint32_t af[2][4][4], bf[2][4][2];
    int arow = warpM * 64 + tq;
    int brow = warpN * 32 + tq;

#pragma unroll
    for (int mi = 0; mi < 4; mi++) {
        af[0][mi][0] = __float_as_uint(sm.mm.As[0][arow + mi * 16    ][tr    ]);
        af[0][mi][1] = __float_as_uint(sm.mm.As[0][arow + mi * 16 + 8][tr    ]);
        af[0][mi][2] = __float_as_uint(sm.mm.As[0][arow + mi * 16    ][tr + 4]);
        af[0][mi][3] = __float_as_uint(sm.mm.As[0][arow + mi * 16 + 8][tr + 4]);
    }
#pragma unroll
    for (int ni = 0; ni < 4; ni++) {
        bf[0][ni][0] = __float_as_uint(sm.mm.Bs[0][brow + ni * 8][tr    ]);
        bf[0][ni][1] = __float_as_uint(sm.mm.Bs[0][brow + ni * 8][tr + 4]);
    }

    int buf = 0, wslot = NSTG - 1;
    for (int kt = 0; kt < nk16; kt++) {
#pragma unroll
        for (int mi = 0; mi < 4; mi++) {
            af[1][mi][0] = __float_as_uint(sm.mm.As[buf][arow + mi * 16    ][8 + tr    ]);
            af[1][mi][1] = __float_as_uint(sm.mm.As[buf][arow + mi * 16 + 8][8 + tr    ]);
            af[1][mi][2] = __float_as_uint(sm.mm.As[buf][arow + mi * 16    ][8 + tr + 4]);
            af[1][mi][3] = __float_as_uint(sm.mm.As[buf][arow + mi * 16 + 8][8 + tr + 4]);
        }
#pragma unroll
        for (int ni = 0; ni < 4; ni++) {
            bf[1][ni][0] = __float_as_uint(sm.mm.Bs[buf][brow + ni * 8][8 + tr    ]);
            bf[1][ni][1] = __float_as_uint(sm.mm.Bs[buf][brow + ni * 8][8 + tr + 4]);
        }
#pragma unroll
        for (int mi = 0; mi < 4; mi++)
#pragma unroll
            for (int ni = 0; ni < 4; ni++)
                mma_tf32(acc[mi][ni], af[0][mi][0], af[0][mi][1],
                         af[0][mi][2], af[0][mi][3],
                         bf[0][ni][0], bf[0][ni][1]);
        int snext = kt + NSTG - 1;
        if (snext < nk16) {
            uint32_t so = (uint32_t)wslot * STGB;
            const float* xp = Xp + snext * 16;
            const float* wp = Wp + snext * 16;
            cpasync16(sa + so, xp);       cpasync16(sa + so + 16, xp + 4);
            cpasync16(sb + so, wp);       cpasync16(sb + so + 16, wp + 4);
        }
        asm volatile("cp.async.commit_group;");
        asm volatile("cp.async.wait_group %0;" :: "n"(NSTG - 2));
        __syncthreads();
        if (++wslot == NSTG) wslot = 0;
        int nb = buf + 1; if (nb == NSTG) nb = 0;
        if (kt + 1 < nk16) {
#pragma unroll
            for (int mi = 0; mi < 4; mi++) {
                af[0][mi][0] = __float_as_uint(sm.mm.As[nb][arow + mi * 16    ][tr    ]);
                af[0][mi][1] = __float_as_uint(sm.mm.As[nb][arow + mi * 16 + 8][tr    ]);
                af[0][mi][2] = __float_as_uint(sm.mm.As[nb][arow + mi * 16    ][tr + 4]);
                af[0][mi][3] = __float_as_uint(sm.mm.As[nb][arow + mi * 16 + 8][tr + 4]);
            }
#pragma unroll
            for (int ni = 0; ni < 4; ni++) {
                bf[0][ni][0] = __float_as_uint(sm.mm.Bs[nb][brow + ni * 8][tr    ]);
                bf[0][ni][1] = __float_as_uint(sm.mm.Bs[nb][brow + ni * 8][tr + 4]);
            }
        }
#pragma unroll
        for (int mi = 0; mi < 4; mi++)
#pragma unroll
            for (int ni = 0; ni < 4; ni++)
                mma_tf32(acc[mi][ni], af[1][mi][0], af[1][mi][1],
                         af[1][mi][2], af[1][mi][3],
                         bf[1][ni][0], bf[1][ni][1]);
        buf = nb;
    }

    if (mode == 3) {
#pragma unroll
        for (int mi = 0; mi < 4; mi++)
#pragma unroll
            for (int h = 0; h < 2; h++) {
                int r = row0 + warpM * 64 + mi * 16 + tq + 8 * h;
#pragma unroll
                for (int ni = 0; ni < 4; ni++) {
                    int c = col0 + warpN * 32 + ni * 8 + 2 * tr;
                    *(float2*)&C[(size_t)r * Nc + c] =
                        make_float2(acc[mi][ni][2 * h], acc[mi][ni][2 * h + 1]);
                }
            }
        return;
    }

    // mode 2: bias + residual + LayerNorm over 128-wide rows (col0 == 0)
#pragma unroll
    for (int mi = 0; mi < 4; mi++)
#pragma unroll
        for (int h = 0; h < 2; h++) {
            int r = row0 + warpM * 64 + mi * 16 + tq + 8 * h;
#pragma unroll
            for (int ni = 0; ni < 4; ni++) {
                int c = warpN * 32 + ni * 8 + 2 * tr;
                float2 rv = *(const float2*)&res[(size_t)r * 128 + c];
                acc[mi][ni][2 * h]     += bias[c]     + rv.x;
                acc[mi][ni][2 * h + 1] += bias[c + 1] + rv.y;
            }
        }
    __syncthreads();
    int cid = warpN * 4 + tr;
#pragma unroll
    for (int mi = 0; mi < 4; mi++)
#pragma unroll
        for (int h = 0; h < 2; h++) {
            int rl = warpM * 64 + mi * 16 + tq + 8 * h;
            float s = 0.f;
#pragma unroll
            for (int ni = 0; ni < 4; ni++) s += acc[mi][ni][2 * h] + acc[mi][ni][2 * h + 1];
            sm.ep.red[rl][cid] = s;
        }
    __syncthreads();
    if (tid < 128) {
        float s = 0.f;
#pragma unroll
        for (int t = 0; t < 16; t++) s += sm.ep.red[tid][t];
        sm.ep.stat[tid] = s * (1.f / 128.f);
    }
    __syncthreads();
    float mean[4][2];
#pragma unroll
    for (int mi = 0; mi < 4; mi++)
#pragma unroll
        for (int h = 0; h < 2; h++)
            mean[mi][h] = sm.ep.stat[warpM * 64 + mi * 16 + tq + 8 * h];
    __syncthreads();
#pragma unroll
    for (int mi = 0; mi < 4; mi++)
#pragma unroll
        for (int h = 0; h < 2; h++) {
            int rl = warpM * 64 + mi * 16 + tq + 8 * h;
            float s = 0.f;
#pragma unroll
            for (int ni = 0; ni < 4; ni++) {
                float d0 = acc[mi][ni][2 * h]     - mean[mi][h];
                float d1 = acc[mi][ni][2 * h + 1] - mean[mi][h];
                s += d0 * d0 + d1 * d1;
            }
            sm.ep.red[rl][cid] = s;
        }
    __syncthreads();
    if (tid < 128) {
        float s = 0.f;
#pragma unroll
        for (int t = 0; t < 16; t++) s += sm.ep.red[tid][t];
        sm.ep.stat[tid] = rsqrtf(s * (1.f / 128.f) + EPSV);
    }
    __syncthreads();
#pragma unroll
    for (int mi = 0; mi < 4; mi++)
#pragma unroll
        for (int h = 0; h < 2; h++) {
            int rl = warpM * 64 + mi * 16 + tq + 8 * h;
            int r = row0 + rl;
            float rs = sm.ep.stat[rl];
#pragma unroll
            for (int ni = 0; ni < 4; ni++) {
                int c = warpN * 32 + ni * 8 + 2 * tr;
                float v0 = (acc[mi][ni][2 * h]     - mean[mi][h]) * rs * lng[c]     + lnb[c];
                float v1 = (acc[mi][ni][2 * h + 1] - mean[mi][h]) * rs * lng[c + 1] + lnb[c + 1];
                *(float2*)&C[(size_t)r * 128 + c] = make_float2(v0, v1);
            }
        }
}

// ========= QKV GEMM, smem-resident A, 4-stage B ring, half output ==========
#define QKV_DYN_BYTES (128 * 132 * 4 + NSTQ * STGF * 4)   // 67584 + 40960

__global__ __launch_bounds__(256, 2)
void qkv_kernel(const float* __restrict__ X, const float* __restrict__ W,
                const float* __restrict__ bias, __half* __restrict__ C)
{
    extern __shared__ float dsm[];
    float* Afull = dsm;                     // [128][132]
    float* BsR   = dsm + 128 * 132;         // [NSTQ][128][20]
#define QA(r, c)    Afull[(r) * 132 + (c)]
#define QB(s, r, c) BsR[(s) * STGF + (r) * 20 + (c)]

    int tid = threadIdx.x;
    int lane = tid & 31, warp = tid >> 5;
    int tq = lane >> 2, tr = lane & 3;
    int warpM = warp & 1, warpN = warp >> 1;
    int row0 = blockIdx.x * 128;

    uint32_t abase = smem_u32(&QA(0, 0));
    const float* Xb = X + (size_t)row0 * 128;
#pragma unroll
    for (int t = 0; t < 16; t++) {
        int m = tid + t * 256;
        int r = m >> 5, c4 = (m & 31) * 4;
        cpasync16(abase + (uint32_t)(r * 132 + c4) * 4, Xb + r * 128 + c4);
    }
    asm volatile("cp.async.commit_group;");

    int glr = tid >> 1, glc = (tid & 1) * 8;
    uint32_t sb = smem_u32(&QB(0, glr, glc));
    const uint32_t STGB = STGF * 4;

#pragma unroll
    for (int s = 0; s < 3; s++) {
        const float* wp = W + (size_t)glr * 128 + s * 16 + glc;
        cpasync16(sb + (uint32_t)s * STGB, wp);
        cpasync16(sb + (uint32_t)s * STGB + 16, wp + 4);
        asm volatile("cp.async.commit_group;");
    }
    asm volatile("cp.async.wait_group 2;");   // A + stage 0 complete
    __syncthreads();

    float acc[4][4][4] = {};
    uint32_t af[2][4][4], bf[2][4][2];
    int arow = warpM * 64 + tq;
    int brow = warpN * 32 + tq;

#pragma unroll
    for (int mi = 0; mi < 4; mi++) {
        af[0][mi][0] = __float_as_uint(QA(arow + mi * 16    , tr    ));
        af[0][mi][1] = __float_as_uint(QA(arow + mi * 16 + 8, tr    ));
        af[0][mi][2] = __float_as_uint(QA(arow + mi * 16    , tr + 4));
        af[0][mi][3] = __float_as_uint(QA(arow + mi * 16 + 8, tr + 4));
    }
#pragma unroll
    for (int ni = 0; ni < 4; ni++) {
        bf[0][ni][0] = __float_as_uint(QB(0, brow + ni * 8, tr    ));
        bf[0][ni][1] = __float_as_uint(QB(0, brow + ni * 8, tr + 4));
    }

    for (int g = 0; g < 24; g++) {
        int kt = g & 7;
        int buf = g & (NSTQ - 1);
        int kb = kt * 16;
#pragma unroll
        for (int mi = 0; mi < 4; mi++) {
            af[1][mi][0] = __float_as_uint(QA(arow + mi * 16    , kb + 8 + tr    ));
            af[1][mi][1] = __float_as_uint(QA(arow + mi * 16 + 8, kb + 8 + tr    ));
            af[1][mi][2] = __float_as_uint(QA(arow + mi * 16    , kb + 8 + tr + 4));
            af[1][mi][3] = __float_as_uint(QA(arow + mi * 16 + 8, kb + 8 + tr + 4));
        }
#pragma unroll
        for (int ni = 0; ni < 4; ni++) {
            bf[1][ni][0] = __float_as_uint(QB(buf, brow + ni * 8, 8 + tr    ));
            bf[1][ni][1] = __float_as_uint(QB(buf, brow + ni * 8, 8 + tr + 4));
        }
#pragma unroll
        for (int mi = 0; mi < 4; mi++)
#pragma unroll
            for (int ni = 0; ni < 4; ni++)
                mma_tf32(acc[mi][ni], af[0][mi][0], af[0][mi][1],
                         af[0][mi][2], af[0][mi][3],
                         bf[0][ni][0], bf[0][ni][1]);
        int gn = g + 3;
        if (gn < 24) {
            int ctn = gn >> 3, ktn = gn & 7;
            const float* wp = W + (size_t)(ctn * 128 + glr) * 128 + ktn * 16 + glc;
            uint32_t so = (uint32_t)(gn & (NSTQ - 1)) * STGB;
            cpasync16(sb + so, wp);   cpasync16(sb + so + 16, wp + 4);
        }
        asm volatile("cp.async.commit_group;");
        asm volatile("cp.async.wait_group 2;");
        __syncthreads();
        if (g + 1 < 24) {
            int k2 = ((g + 1) & 7) * 16;
            int b2 = (g + 1) & (NSTQ - 1);
#pragma unroll
            for (int mi = 0; mi < 4; mi++) {
                af[0][mi][0] = __float_as_uint(QA(arow + mi * 16    , k2 + tr    ));
                af[0][mi][1] = __float_as_uint(QA(arow + mi * 16 + 8, k2 + tr    ));
                af[0][mi][2] = __float_as_uint(QA(arow + mi * 16    , k2 + tr + 4));
                af[0][mi][3] = __float_as_uint(QA(arow + mi * 16 + 8, k2 + tr + 4));
            }
#pragma unroll
            for (int ni = 0; ni < 4; ni++) {
                bf[0][ni][0] = __float_as_uint(QB(b2, brow + ni * 8, tr    ));
                bf[0][ni][1] = __float_as_uint(QB(b2, brow + ni * 8, tr + 4));
            }
        }
#pragma unroll
        for (int mi = 0; mi < 4; mi++)
#pragma unroll
            for (int ni = 0; ni < 4; ni++)
                mma_tf32(acc[mi][ni], af[1][mi][0], af[1][mi][1],
                         af[1][mi][2], af[1][mi][3],
                         bf[1][ni][0], bf[1][ni][1]);
        if (kt == 7) {
            int cb = (g >> 3) * 128;
#pragma unroll
            for (int mi = 0; mi < 4; mi++)
#pragma unroll
                for (int h = 0; h < 2; h++) {
                    int r = row0 + warpM * 64 + mi * 16 + tq + 8 * h;
#pragma unroll
                    for (int ni = 0; ni < 4; ni++) {
                        int c = warpN * 32 + ni * 8 + 2 * tr;
                        float v0 = acc[mi][ni][2 * h]     + bias[cb + c];
                        float v1 = acc[mi][ni][2 * h + 1] + bias[cb + c + 1];
                        *(__half2*)&C[(size_t)r * 384 + cb + c] =
                            __floats2half2_rn(v0, v1);
                        acc[mi][ni][2 * h] = 0.f;
                        acc[mi][ni][2 * h + 1] = 0.f;
                    }
                }
        }
    }
#undef QA
#undef QB
}

// ======== fp16 tensor-core attention, one CTA per (seq, head) ==============
// smem (bytes): region0 = S float [128][132] (67584; aliases qh/kh during load)
//   qh half[128][40] @0 (10240), kh half[128][40] @10240
// vt_h half[32][136]  @67584 (8704)
// sp_h half[128][136] @76288 (34816)      total 111104 B
#define ATTN_SMEM_BYTES (128 * 132 * 4 + 32 * 136 * 2 + 128 * 136 * 2)

__global__ __launch_bounds__(256)
void attn_mma_kernel(const __half* __restrict__ qkv, float* __restrict__ out)
{
    extern __shared__ char smc[];
    float  (*sp)[132]  = (float(*)[132])smc;
    __half (*qh)[40]   = (__half(*)[40])smc;
    __half (*kh)[40]   = (__half(*)[40])(smc + 10240);
    __half (*vth)[136] = (__half(*)[136])(smc + 67584);
    __half (*sph)[136] = (__half(*)[136])(smc + 76288);

    int s  = blockIdx.x >> 2;
    int hh = blockIdx.x & 3;
    int tid = threadIdx.x;
    int lane = tid & 31, warp = tid >> 5;
    int tq = lane >> 2, tr = lane & 3;
    int warpM = warp & 1, warpN = warp >> 1;

    // zero pads: qh/kh rows 121..127 (cols 0..31 used), vth key-cols 121..127
    for (int idx = tid; idx < 7 * 32; idx += 256) {
        int r = 121 + idx / 32, c = idx % 32;
        qh[r][c] = __float2half(0.f);
        kh[r][c] = __float2half(0.f);
    }
    for (int idx = tid; idx < 32 * 7; idx += 256) {
        int d = idx / 7, c = 121 + idx % 7;
        vth[d][c] = __float2half(0.f);
    }

    const __half* base = qkv + (size_t)s * NT * 384 + hh * HDH;
    for (int idx = tid; idx < NT * 8; idx += 256) {
        int n = idx >> 3, d4 = (idx & 7) * 4;
        const __half* bp = base + (size_t)n * 384 + d4;
        __half2 q01 = *(const __half2*)(bp);
        __half2 q23 = *(const __half2*)(bp + 2);
        __half2 k01 = *(const __half2*)(bp + 128);
        __half2 k23 = *(const __half2*)(bp + 130);
        __half2 v01 = *(const __half2*)(bp + 256);
        __half2 v23 = *(const __half2*)(bp + 258);
        *(__half2*)&qh[n][d4]     = q01;
        *(__half2*)&qh[n][d4 + 2] = q23;
        *(__half2*)&kh[n][d4]     = k01;
        *(__half2*)&kh[n][d4 + 2] = k23;
        vth[d4 + 0][n] = __low2half(v01);
        vth[d4 + 1][n] = __high2half(v01);
        vth[d4 + 2][n] = __low2half(v23);
        vth[d4 + 3][n] = __high2half(v23);
    }
    __syncthreads();

    // ---- S = Q @ K^T  (128x128x32, fp16 k16 x 2) ----
    float acc[4][4][4] = {};
#pragma unroll
    for (int k16 = 0; k16 < 32; k16 += 16) {
        uint32_t af[4][4], bf[4][2];
#pragma unroll
        for (int mi = 0; mi < 4; mi++) {
            int ar = warpM * 64 + mi * 16 + tq;
            af[mi][0] = *(const uint32_t*)&qh[ar    ][k16 + 2 * tr    ];
            af[mi][1] = *(const uint32_t*)&qh[ar + 8][k16 + 2 * tr    ];
            af[mi][2] = *(const uint32_t*)&qh[ar    ][k16 + 2 * tr + 8];
            af[mi][3] = *(const uint32_t*)&qh[ar + 8][k16 + 2 * tr + 8];
        }
#pragma unroll
        for (int ni = 0; ni < 4; ni++) {
            int br = warpN * 32 + ni * 8 + tq;
            bf[ni][0] = *(const uint32_t*)&kh[br][k16 + 2 * tr    ];
            bf[ni][1] = *(const uint32_t*)&kh[br][k16 + 2 * tr + 8];
        }
#pragma unroll
        for (int mi = 0; mi < 4; mi++)
#pragma unroll
            for (int ni = 0; ni < 4; ni++)
                mma_f16(acc[mi][ni], af[mi][0], af[mi][1], af[mi][2], af[mi][3],
                        bf[ni][0], bf[ni][1]);
    }
    __syncthreads();   // qh/kh reads done before sp overwrites them

#pragma unroll
    for (int mi = 0; mi < 4; mi++)
#pragma unroll
        for (int h = 0; h < 2; h++) {
            int r = warpM * 64 + mi * 16 + tq + 8 * h;
#pragma unroll
            for (int ni = 0; ni < 4; ni++) {
                int c = warpN * 32 + ni * 8 + 2 * tr;
                *(float2*)&sp[r][c] = make_float2(acc[mi][ni][2 * h], acc[mi][ni][2 * h + 1]);
            }
        }
    __syncthreads();

    // ---- softmax: thread pair per row; result written as half into sph ----
    const float scale = 0.17677669529663687f;
    {
        int r2 = tid >> 1, hf = tid & 1;
        float* row = &sp[r2][0];
        float4* rowq = (float4*)(row + hf * 64);
        int nq = hf ? 14 : 16;               // half0: cols 0..63; half1: 64..119
        float mx = hf ? row[120] : -1e30f;
        for (int q = 0; q < nq; q++) {
            float4 v = rowq[q];
            mx = fmaxf(mx, fmaxf(fmaxf(v.x, v.y), fmaxf(v.z, v.w)));
        }
        mx = fmaxf(mx, __shfl_xor_sync(0xffffffffu, mx, 1));
        float sum = 0.f;
        for (int q = 0; q < nq; q++) {
            float4 v = rowq[q];
            v.x = __expf((v.x - mx) * scale);
            v.y = __expf((v.y - mx) * scale);
            v.z = __expf((v.z - mx) * scale);
            v.w = __expf((v.w - mx) * scale);
            rowq[q] = v;
            sum += v.x + v.y + v.z + v.w;
        }
        float e120 = 0.f;
        if (hf) {
            e120 = __expf((row[120] - mx) * scale);
            sum += e120;
        }
        sum += __shfl_xor_sync(0xffffffffu, sum, 1);
        float inv = 1.f / sum;
        __half2* outh = (__half2*)&sph[r2][hf * 64];
        for (int q = 0; q < nq; q++) {
            float4 v = rowq[q];
            outh[2 * q]     = __floats2half2_rn(v.x * inv, v.y * inv);
            outh[2 * q + 1] = __floats2half2_rn(v.z * inv, v.w * inv);
        }
        if (hf) {
            // cols 120..127: e120*inv then zeros
            outh[28] = __floats2half2_rn(e120 * inv, 0.f);
            outh[29] = __floats2half2_rn(0.f, 0.f);
            outh[30] = __floats2half2_rn(0.f, 0.f);
            outh[31] = __floats2half2_rn(0.f, 0.f);
        }
    }
    __syncthreads();

    // ---- O = P @ V  (128x32x128, fp16 k16 x 8), V^T in vth[dim][key] ------
    float pacc[4][4] = {};
#pragma unroll
    for (int k16 = 0; k16 < 128; k16 += 16) {
        uint32_t af[4][4], bf[2];
#pragma unroll
        for (int mi = 0; mi < 4; mi++) {
            int ar = warpM * 64 + mi * 16 + tq;
            af[mi][0] = *(const uint32_t*)&sph[ar    ][k16 + 2 * tr    ];
            af[mi][1] = *(const uint32_t*)&sph[ar + 8][k16 + 2 * tr    ];
            af[mi][2] = *(const uint32_t*)&sph[ar    ][k16 + 2 * tr + 8];
            af[mi][3] = *(const uint32_t*)&sph[ar + 8][k16 + 2 * tr + 8];
        }
        int bn = warpN * 8 + tq;
        bf[0] = *(const uint32_t*)&vth[bn][k16 + 2 * tr    ];
        bf[1] = *(const uint32_t*)&vth[bn][k16 + 2 * tr + 8];
#pragma unroll
        for (int mi = 0; mi < 4; mi++)
            mma_f16(pacc[mi], af[mi][0], af[mi][1], af[mi][2], af[mi][3],
                    bf[0], bf[1]);
    }

#pragma unroll
    for (int mi = 0; mi < 4; mi++)
#pragma unroll
        for (int h = 0; h < 2; h++) {
            int r = warpM * 64 + mi * 16 + tq + 8 * h;
            if (r < NT) {
                int c = warpN * 8 + 2 * tr;
                *(float2*)&out[((size_t)s * NT + r) * HDIM + hh * HDH + c] =
                    make_float2(pacc[mi][2 * h], pacc[mi][2 * h + 1]);
            }
        }
}

// ========== fused FFN: x = LN(x + relu(x@W1^T+b1)@W2^T + b2) ==============
#define FFN_DYN_BYTES (NSTG * STGF * 4 + 128 * 132 * 4)   // 30720 + 67584

__global__ __launch_bounds__(256, 2)
void ffn_kernel(const float* __restrict__ X,
                const float* __restrict__ W1, const float* __restrict__ b1,
                const float* __restrict__ W2, const float* __restrict__ b2,
                const float* __restrict__ lng, const float* __restrict__ lnb,
                float* __restrict__ C)
{
    extern __shared__ float dsm[];
    float* BsR = dsm;
    float* AR  = dsm + NSTG * STGF;
#define FB(s, r, c) BsR[(s) * STGF + (r) * 20 + (c)]
#define FA(s, r, c) AR[(s) * STGF + (r) * 20 + (c)]
#define HS(r, c)    AR[(r) * 132 + (c)]

    int tid = threadIdx.x;
    int lane = tid & 31, warp = tid >> 5;
    int tq = lane >> 2, tr = lane & 3;
    int warpM = warp & 1, warpN = warp >> 1;
    int row0 = blockIdx.x * 128;

    int glr = tid >> 1;
    int glc = (tid & 1) * 8;
    const float* Xp  = X  + (size_t)(row0 + glr) * 128 + glc;
    const float* W1p = W1 + (size_t)glr * 128 + glc;
    const float* W2p = W2 + (size_t)glr * 128 + glc;
    uint32_t sa = smem_u32(&FA(0, glr, glc));
    uint32_t sb = smem_u32(&FB(0, glr, glc));
    const uint32_t STGB = STGF * 4;

    int arow = warpM * 64 + tq;
    int brow = warpN * 32 + tq;
    float acc[4][4][4] = {};
    uint32_t af[2][4][4], bf[2][4][2];

#pragma unroll
    for (int s = 0; s < NSTG - 1; s++) {
        uint32_t so = (uint32_t)s * STGB;
        cpasync16(sa + so, Xp + s * 16);       cpasync16(sa + so + 16, Xp + s * 16 + 4);
        cpasync16(sb + so, W1p + s * 16);      cpasync16(sb + so + 16, W1p + s * 16 + 4);
        asm volatile("cp.async.commit_group;");
    }
    asm volatile("cp.async.wait_group %0;" :: "n"(NSTG - 2));
    __syncthreads();

#pragma unroll
    for (int mi = 0; mi < 4; mi++) {
        af[0][mi][0] = __float_as_uint(FA(0, arow + mi * 16    , tr    ));
        af[0][mi][1] = __float_as_uint(FA(0, arow + mi * 16 + 8, tr    ));
        af[0][mi][2] = __float_as_uint(FA(0, arow + mi * 16    , tr + 4));
        af[0][mi][3] = __float_as_uint(FA(0, arow + mi * 16 + 8, tr + 4));
    }
#pragma unroll
    for (int ni = 0; ni < 4; ni++) {
        bf[0][ni][0] = __float_as_uint(FB(0, brow + ni * 8, tr    ));
        bf[0][ni][1] = __float_as_uint(FB(0, brow + ni * 8, tr + 4));
    }

    int buf = 0, wslot = NSTG - 1;
    for (int kt = 0; kt < 8; kt++) {
#pragma unroll
        for (int mi = 0; mi < 4; mi++) {
            af[1][mi][0] = __float_as_uint(FA(buf, arow + mi * 16    , 8 + tr    ));
            af[1][mi][1] = __float_as_uint(FA(buf, arow + mi * 16 + 8, 8 + tr    ));
            af[1][mi][2] = __float_as_uint(FA(buf, arow + mi * 16    , 8 + tr + 4));
            af[1][mi][3] = __float_as_uint(FA(buf, arow + mi * 16 + 8, 8 + tr + 4));
        }
#pragma unroll
        for (int ni = 0; ni < 4; ni++) {
            bf[1][ni][0] = __float_as_uint(FB(buf, brow + ni * 8, 8 + tr    ));
            bf[1][ni][1] = __float_as_uint(FB(buf, brow + ni * 8, 8 + tr + 4));
        }
#pragma unroll
        for (int mi = 0; mi < 4; mi++)
#pragma unroll
            for (int ni = 0; ni < 4; ni++)
                mma_tf32(acc[mi][ni], af[0][mi][0], af[0][mi][1],
                         af[0][mi][2], af[0][mi][3],
                         bf[0][ni][0], bf[0][ni][1]);
        int snext = kt + NSTG - 1;
        if (snext < 8) {
            uint32_t so = (uint32_t)wslot * STGB;
            cpasync16(sa + so, Xp + snext * 16);   cpasync16(sa + so + 16, Xp + snext * 16 + 4);
            cpasync16(sb + so, W1p + snext * 16);  cpasync16(sb + so + 16, W1p + snext * 16 + 4);
        }
        asm volatile("cp.async.commit_group;");
        asm volatile("cp.async.wait_group %0;" :: "n"(NSTG - 2));
        __syncthreads();
        if (++wslot == NSTG) wslot = 0;
        int nb = buf + 1; if (nb == NSTG) nb = 0;
        if (kt + 1 < 8) {
#pragma unroll
            for (int mi = 0; mi < 4; mi++) {
                af[0][mi][0] = __float_as_uint(FA(nb, arow + mi * 16    , tr    ));
                af[0][mi][1] = __float_as_uint(FA(nb, arow + mi * 16 + 8, tr    ));
                af[0][mi][2] = __float_as_uint(FA(nb, arow + mi * 16    , tr + 4));
                af[0][mi][3] = __float_as_uint(FA(nb, arow + mi * 16 + 8, tr + 4));
            }
#pragma unroll
            for (int ni = 0; ni < 4; ni++) {
                bf[0][ni][0] = __float_as_uint(FB(nb, brow + ni * 8, tr    ));
                bf[0][ni][1] = __float_as_uint(FB(nb, brow + ni * 8, tr + 4));
            }
        }
#pragma unroll
        for (int mi = 0; mi < 4; mi++)
#pragma unroll
            for (int ni = 0; ni < 4; ni++)
                mma_tf32(acc[mi][ni], af[1][mi][0], af[1][mi][1],
                         af[1][mi][2], af[1][mi][3],
                         bf[1][ni][0], bf[1][ni][1]);
        buf = nb;
    }

#pragma unroll
    for (int s = 0; s < NSTG - 1; s++) {
        uint32_t so = (uint32_t)s * STGB;
        cpasync16(sb + so, W2p + s * 16);      cpasync16(sb + so + 16, W2p + s * 16 + 4);
        asm volatile("cp.async.commit_group;");
    }

#pragma unroll
    for (int mi = 0; mi < 4; mi++)
#pragma unroll
        for (int h2 = 0; h2 < 2; h2++) {
            int r = warpM * 64 + mi * 16 + tq + 8 * h2;
#pragma unroll
            for (int ni = 0; ni < 4; ni++) {
                int c = warpN * 32 + ni * 8 + 2 * tr;
                HS(r, c)     = fmaxf(acc[mi][ni][2 * h2]     + b1[c],     0.f);
                HS(r, c + 1) = fmaxf(acc[mi][ni][2 * h2 + 1] + b1[c + 1], 0.f);
            }
        }
    asm volatile("cp.async.wait_group %0;" :: "n"(NSTG - 2));
    __syncthreads();

#pragma unroll
    for (int mi = 0; mi < 4; mi++)
#pragma unroll
        for (int ni = 0; ni < 4; ni++)
#pragma unroll
            for (int q = 0; q < 4; q++) acc[mi][ni][q] = 0.f;

#pragma unroll
    for (int mi = 0; mi < 4; mi++) {
        af[0][mi][0] = __float_as_uint(HS(arow + mi * 16    , tr    ));
        af[0][mi][1] = __float_as_uint(HS(arow + mi * 16 + 8, tr    ));
        af[0][mi][2] = __float_as_uint(HS(arow + mi * 16    , tr + 4));
        af[0][mi][3] = __float_as_uint(HS(arow + mi * 16 + 8, tr + 4));
    }
#pragma unroll
    for (int ni = 0; ni < 4; ni++) {
        bf[0][ni][0] = __float_as_uint(FB(0, brow + ni * 8, tr    ));
        bf[0][ni][1] = __float_as_uint(FB(0, brow + ni * 8, tr + 4));
    }

    buf = 0; wslot = NSTG - 1;
    for (int kt = 0; kt < 8; kt++) {
        int kb = kt * 16;
#pragma unroll
        for (int mi = 0; mi < 4; mi++) {
            af[1][mi][0] = __float_as_uint(HS(arow + mi * 16    , kb + 8 + tr    ));
            af[1][mi][1] = __float_as_uint(HS(arow + mi * 16 + 8, kb + 8 + tr    ));
            af[1][mi][2] = __float_as_uint(HS(arow + mi * 16    , kb + 8 + tr + 4));
            af[1][mi][3] = __float_as_uint(HS(arow + mi * 16 + 8, kb + 8 + tr + 4));
        }
#pragma unroll
        for (int ni = 0; ni < 4; ni++) {
            bf[1][ni][0] = __float_as_uint(FB(buf, brow + ni * 8, 8 + tr    ));
            bf[1][ni][1] = __float_as_uint(FB(buf, brow + ni * 8, 8 + tr + 4));
        }
#pragma unroll
        for (int mi = 0; mi < 4; mi++)
#pragma unroll
            for (int ni = 0; ni < 4; ni++)
                mma_tf32(acc[mi][ni], af[0][mi][0], af[0][mi][1],
                         af[0][mi][2], af[0][mi][3],
                         bf[0][ni][0], bf[0][ni][1]);
        int snext = kt + NSTG - 1;
        if (snext < 8) {
            uint32_t so = (uint32_t)wslot * STGB;
            cpasync16(sb + so, W2p + snext * 16);  cpasync16(sb + so + 16, W2p + snext * 16 + 4);
        }
        asm volatile("cp.async.commit_group;");
        asm volatile("cp.async.wait_group %0;" :: "n"(NSTG - 2));
        __syncthreads();
        if (++wslot == NSTG) wslot = 0;
        int nb = buf + 1; if (nb == NSTG) nb = 0;
        if (kt + 1 < 8) {
            int kn = (kt + 1) * 16;
#pragma unroll
            for (int mi = 0; mi < 4; mi++) {
                af[0][mi][0] = __float_as_uint(HS(arow + mi * 16    , kn + tr    ));
                af[0][mi][1] = __float_as_uint(HS(arow + mi * 16 + 8, kn + tr    ));
                af[0][mi][2] = __float_as_uint(HS(arow + mi * 16    , kn + tr + 4));
                af[0][mi][3] = __float_as_uint(HS(arow + mi * 16 + 8, kn + tr + 4));
            }
#pragma unroll
            for (int ni = 0; ni < 4; ni++) {
                bf[0][ni][0] = __float_as_uint(FB(nb, brow + ni * 8, tr    ));
                bf[0][ni][1] = __float_as_uint(FB(nb, brow + ni * 8, tr + 4));
            }
        }
#pragma unroll
        for (int mi = 0; mi < 4; mi++)
#pragma unroll
            for (int ni = 0; ni < 4; ni++)
                mma_tf32(acc[mi][ni], af[1][mi][0], af[1][mi][1],
                         af[1][mi][2], af[1][mi][3],
                         bf[1][ni][0], bf[1][ni][1]);
        buf = nb;
    }

    float* red  = dsm;
    float* stat = dsm + 128 * 17;
#pragma unroll
    for (int mi = 0; mi < 4; mi++)
#pragma unroll
        for (int h2 = 0; h2 < 2; h2++) {
            int r = row0 + warpM * 64 + mi * 16 + tq + 8 * h2;
#pragma unroll
            for (int ni = 0; ni < 4; ni++) {
                int c = warpN * 32 + ni * 8 + 2 * tr;
                float2 rv = *(const float2*)&X[(size_t)r * 128 + c];
                acc[mi][ni][2 * h2]     += b2[c]     + rv.x;
                acc[mi][ni][2 * h2 + 1] += b2[c + 1] + rv.y;
            }
        }
    __syncthreads();
    int cid = warpN * 4 + tr;
#pragma unroll
    for (int mi = 0; mi < 4; mi++)
#pragma unroll
        for (int h2 = 0; h2 < 2; h2++) {
            int rl = warpM * 64 + mi * 16 + tq + 8 * h2;
            float s = 0.f;
#pragma unroll
            for (int ni = 0; ni < 4; ni++) s += acc[mi][ni][2 * h2] + acc[mi][ni][2 * h2 + 1];
            red[rl * 17 + cid] = s;
        }
    __syncthreads();
    if (tid < 128) {
        float s = 0.f;
#pragma unroll
        for (int t = 0; t < 16; t++) s += red[tid * 17 + t];
        stat[tid] = s * (1.f / 128.f);
    }
    __syncthreads();
    float mean[4][2];
#pragma unroll
    for (int mi = 0; mi < 4; mi++)
#pragma unroll
        for (int h2 = 0; h2 < 2; h2++)
            mean[mi][h2] = stat[warpM * 64 + mi * 16 + tq + 8 * h2];
    __syncthreads();
#pragma unroll
    for (int mi = 0; mi < 4; mi++)
#pragma unroll
        for (int h2 = 0; h2 < 2; h2++) {
            int rl = warpM * 64 + mi * 16 + tq + 8 * h2;
            float s = 0.f;
#pragma unroll
            for (int ni = 0; ni < 4; ni++) {
                float d0 = acc[mi][ni][2 * h2]     - mean[mi][h2];
                float d1 = acc[mi][ni][2 * h2 + 1] - mean[mi][h2];
                s += d0 * d0 + d1 * d1;
            }
            red[rl * 17 + cid] = s;
        }
    __syncthreads();
    if (tid < 128) {
        float s = 0.f;
#pragma unroll
        for (int t = 0; t < 16; t++) s += red[tid * 17 + t];
        stat[tid] = rsqrtf(s * (1.f / 128.f) + EPSV);
    }
    __syncthreads();
#pragma unroll
    for (int mi = 0; mi < 4; mi++)
#pragma unroll
        for (int h2 = 0; h2 < 2; h2++) {
            int rl = warpM * 64 + mi * 16 + tq + 8 * h2;
            int r = row0 + rl;
            float rs = stat[rl];
#pragma unroll
            for (int ni = 0; ni < 4; ni++) {
                int c = warpN * 32 + ni * 8 + 2 * tr;
                float v0 = (acc[mi][ni][2 * h2]     - mean[mi][h2]) * rs * lng[c]     + lnb[c];
                float v1 = (acc[mi][ni][2 * h2 + 1] - mean[mi][h2]) * rs * lng[c + 1] + lnb[c + 1];
                *(float2*)&C[(size_t)r * 128 + c] = make_float2(v0, v1);
            }
        }
#undef FB
#undef FA
#undef HS
}

// ------- final: reduce split-K partials + bias + LayerNorm over 256 -------
__global__ void out_ln_kernel(const float* __restrict__ part,
                              const float* __restrict__ b_out,
                              const float* __restrict__ g,
                              const float* __restrict__ b,
                              float* __restrict__ out)
{
    int row = blockIdx.x, t = threadIdx.x;
    size_t idx = (size_t)row * OUTD + t;
    float v = b_out[t];
#pragma unroll
    for (int z = 0; z < SPLITK; z++) v += part[(size_t)z * SEQ * OUTD + idx];
    __shared__ float red[9];
    int lane = t & 31, warp = t >> 5;
    float s = v;
#pragma unroll
    for (int o = 16; o; o >>= 1) s += __shfl_xor_sync(0xffffffffu, s, o);
    if (lane == 0) red[warp] = s;
    __syncthreads();
    if (t == 0) { float tot = 0; for (int i = 0; i < 8; i++) tot += red[i]; red[8] = tot; }
    __syncthreads();
    float mean = red[8] * (1.f / 256.f);
    float d = v - mean;
    float s2 = d * d;
#pragma unroll
    for (int o = 16; o; o >>= 1) s2 += __shfl_xor_sync(0xffffffffu, s2, o);
    __syncthreads();
    if (lane == 0) red[warp] = s2;
    __syncthreads();
    if (t == 0) { float tot = 0; for (int i = 0; i < 8; i++) tot += red[i]; red[8] = tot; }
    __syncthreads();
    float var = red[8] * (1.f / 256.f);
    out[idx] = d * rsqrtf(var + EPSV) * g[t] + b[t];
}

// ---------------- launch ---------------------------------------------------
extern "C" void kernel_launch(void* const* d_in, const int* in_sizes, int n_in,
                              void* d_out, int out_size)
{
    const float* forest = (const float*)d_in[0];
    const int*   perm   = (const int*)  d_in[2];
    const float* w_in   = (const float*)d_in[3];
    const float* b_in   = (const float*)d_in[4];
    const float* qkv_w  = (const float*)d_in[5];
    const float* qkv_b  = (const float*)d_in[6];
    const float* proj_w = (const float*)d_in[7];
    const float* proj_b = (const float*)d_in[8];
    const float* ff1_w  = (const float*)d_in[9];
    const float* ff1_b  = (const float*)d_in[10];
    const float* ff2_w  = (const float*)d_in[11];
    const float* ff2_b  = (const float*)d_in[12];
    const float* ln1_g  = (const float*)d_in[13];
    const float* ln1_b  = (const float*)d_in[14];
    const float* ln2_g  = (const float*)d_in[15];
    const float* ln2_b  = (const float*)d_in[16];
    const float* w_out  = (const float*)d_in[17];
    const float* b_out  = (const float*)d_in[18];
    const float* lnf_g  = (const float*)d_in[19];
    const float* lnf_b  = (const float*)d_in[20];

    float *xb, *ab, *pb;
    __half* qb;
    cudaGetSymbolAddress((void**)&xb, g_x);
    cudaGetSymbolAddress((void**)&qb, g_qkv);
    cudaGetSymbolAddress((void**)&ab, g_att);
    cudaGetSymbolAddress((void**)&pb, g_py);

    cudaFuncSetAttribute(qkv_kernel,
                         cudaFuncAttributeMaxDynamicSharedMemorySize, QKV_DYN_BYTES);
    cudaFuncSetAttribute(ffn_kernel,
                         cudaFuncAttributeMaxDynamicSharedMemorySize, FFN_DYN_BYTES);
    cudaFuncSetAttribute(attn_mma_kernel,
                         cudaFuncAttributeMaxDynamicSharedMemorySize, ATTN_SMEM_BYTES);

    embed_kernel<<<MTOK / 16, 128>>>(forest, perm, w_in, b_in, xb);

    const int GR = MTOK / 128;  // 1936
    for (int l = 0; l < 2; l++) {
        qkv_kernel<<<GR, 256, QKV_DYN_BYTES>>>(
            xb, qkv_w + (size_t)l * 384 * 128, qkv_b + l * 384, qb);
        attn_mma_kernel<<<SEQ * NHEAD, 256, ATTN_SMEM_BYTES>>>(qb, ab);
        gemm_tf32_kernel<<<dim3(1, GR), 256>>>(
            ab, proj_w + (size_t)l * 128 * 128, proj_b + l * 128,
            xb, ln1_g + l * 128, ln1_b + l * 128, xb, MTOK, 128, 128, 128, 2);
        ffn_kernel<<<GR, 256, FFN_DYN_BYTES>>>(
            xb, ff1_w + (size_t)l * 128 * 128, ff1_b + l * 128,
            ff2_w + (size_t)l * 128 * 128, ff2_b + l * 128,
            ln2_g + l * 128, ln2_b + l * 128, xb);
    }

    // output projection: split-K = 11 in one launch (15488 = 11 * 1408)
    gemm_tf32_kernel<<<dim3(OUTD / 128, SEQ / 128, SPLITK), 256>>>(
        xb, w_out, nullptr, nullptr, nullptr, nullptr,
        pb, SEQ, OUTD, KBIG, KBIG / SPLITK, 3);
    out_ln_kernel<<<SEQ, 256>>>(pb, b_out, lnf_g, lnf_b, (float*)d_out);
}